// round 14
// baseline (speedup 1.0000x reference)
#include <cuda_runtime.h>
#include <cuda_bf16.h>
#include <cstdint>

#define BP 512
#define CC 96
#define TT 128
#define JJ 24
#define ZZ 256
#define CT 12288
#define N2 1024

__device__ __nv_bfloat16  g_qsb[(size_t)N2 * CT];    // decoded motion bf16
__device__ __nv_bfloat16  g_dqsb[(size_t)BP * CT];   // d f / d qs (bf16)
__device__ float          g_grad[(size_t)BP * ZZ];   // grad wrt latent[:,0]
__device__ double         g_acc[6];                  // root joints fk kld disp cons
__device__ unsigned int   g_cnt;                     // cons arrival counter
__device__ __nv_bfloat16  g_W2[(size_t)ZZ * CT];     // W bf16, [z][ct] (filled by gemm1)
__device__ uint32_t       g_W1[(size_t)(ZZ / 2) * CT]; // W bf16 k-pair packed [k2][n]
__device__ __nv_bfloat16  g_latb[(size_t)N2 * ZZ];   // latent bf16

// ---------------------------------------------------------------------------
__device__ __forceinline__ float blockReduce(float v, float* sm) {
#pragma unroll
    for (int o = 16; o > 0; o >>= 1) v += __shfl_down_sync(0xffffffffu, v, o);
    int lane = threadIdx.x & 31, w = threadIdx.x >> 5;
    if (lane == 0) sm[w] = v;
    __syncthreads();
    v = 0.f;
    if (threadIdx.x < 32) {
        int nw = (blockDim.x + 31) >> 5;
        v = (threadIdx.x < nw) ? sm[threadIdx.x] : 0.f;
#pragma unroll
        for (int o = 16; o > 0; o >>= 1) v += __shfl_down_sync(0xffffffffu, v, o);
    }
    return v;
}

// ---------------------------------------------------------------------------
// cvt: W1 + latent -> bf16, zero-init, AND disp/KLD reductions (idle-BW host).
__global__ void cvt_kernel(const float* __restrict__ W, const float* __restrict__ lat,
                           const float* __restrict__ id, const float* __restrict__ td,
                           const float* __restrict__ mu, const float* __restrict__ lv)
{
    __shared__ float s_red[32];
    const int NW1 = (ZZ / 2) * CT;       // 1572864
    const int NL  = (N2 * ZZ) / 2;       // 131072
    int i = blockIdx.x * blockDim.x + threadIdx.x;
    if (i < BP * ZZ) g_grad[i] = 0.f;
    if (i < 6)       g_acc[i] = 0.0;
    if (i == 6)      g_cnt = 0u;
    if (i < NW1) {
        int k2 = i / CT, n = i - k2 * CT;
        float lo = W[(size_t)(2 * k2) * CT + n];
        float hi = W[(size_t)(2 * k2 + 1) * CT + n];
        __nv_bfloat162 h = __floats2bfloat162_rn(lo, hi);
        g_W1[i] = *reinterpret_cast<uint32_t*>(&h);
    } else if (i < NW1 + NL) {
        int j = i - NW1;
        float2 v = reinterpret_cast<const float2*>(lat)[j];
        reinterpret_cast<__nv_bfloat162*>(g_latb)[j] = __floats2bfloat162_rn(v.x, v.y);
    }
    // disp MSE + KLD (grid-stride)
    {
        const int stride = gridDim.x * blockDim.x;
        float sd = 0.f, sk = 0.f;
        for (int k = i; k < BP * 2 * 3 * TT; k += stride) {
            float df = id[k] - td[k]; sd += df * df;
        }
        for (int k = i; k < N2 * ZZ; k += stride) {
            float m = mu[k], l = lv[k];
            sk += 1.0f + l - m * m - expf(l);
        }
        float r = blockReduce(sd, s_red);
        if (threadIdx.x == 0 && r != 0.f) atomicAdd(&g_acc[4], (double)r);
        __syncthreads();
        r = blockReduce(sk, s_red);
        if (threadIdx.x == 0 && r != 0.f) atomicAdd(&g_acc[3], (double)r);
    }
}

// ---------------------------------------------------------------------------
__device__ __forceinline__ void cp16(uint32_t dst, const void* src) {
    asm volatile("cp.async.ca.shared.global [%0], [%1], 16;\n" :: "r"(dst), "l"(src));
}
#define CP_COMMIT() asm volatile("cp.async.commit_group;\n")
#define CP_WAIT1()  asm volatile("cp.async.wait_group 1;\n")
#define CP_WAIT2()  asm volatile("cp.async.wait_group 2;\n")

__device__ __forceinline__ void mma_bf16(float& c0, float& c1, float& c2, float& c3,
                                         uint32_t a0, uint32_t a1, uint32_t a2, uint32_t a3,
                                         uint32_t b0, uint32_t b1)
{
    asm volatile("mma.sync.aligned.m16n8k16.row.col.f32.bf16.bf16.f32 "
                 "{%0,%1,%2,%3}, {%4,%5,%6,%7}, {%8,%9}, {%0,%1,%2,%3};"
                 : "+f"(c0), "+f"(c1), "+f"(c2), "+f"(c3)
                 : "r"(a0), "r"(a1), "r"(a2), "r"(a3), "r"(b0), "r"(b1));
}

__device__ __forceinline__ void ldsm_x4(uint32_t* r, uint32_t addr) {
    asm volatile("ldmatrix.sync.aligned.m8n8.x4.shared.b16 {%0,%1,%2,%3}, [%4];"
                 : "=r"(r[0]), "=r"(r[1]), "=r"(r[2]), "=r"(r[3]) : "r"(addr));
}
__device__ __forceinline__ void ldsm_x2(uint32_t* r, uint32_t addr) {
    asm volatile("ldmatrix.sync.aligned.m8n8.x2.shared.b16 {%0,%1}, [%2];"
                 : "=r"(r[0]), "=r"(r[1]) : "r"(addr));
}

// ---------------------------------------------------------------------------
// GEMM1 (bf16 m16n8k16, cp.async 2-stage, A-frags via ldmatrix):
// g_qsb = latb(1024x256)@W1 + base. Also converts W -> g_W2 (for gemm2).
__global__ __launch_bounds__(256, 2) void gemm1_tc(const float* __restrict__ base,
                                                   const float* __restrict__ W)
{
    extern __shared__ uint32_t smem[];
    uint32_t* AsU = smem;                 // 2 * 2560
    uint32_t* BsU = smem + 5120;          // 2 * 2176
    const uint32_t sA = (uint32_t)__cvta_generic_to_shared(AsU);
    const uint32_t sB = (uint32_t)__cvta_generic_to_shared(BsU);

    const int tid  = threadIdx.x;
    const int lane = tid & 31;
    const int wid  = tid >> 5;
    const int wm   = wid & 1;
    const int wn   = wid >> 1;
    const int g    = lane >> 2;
    const int tg   = lane & 3;
    const int bm   = blockIdx.y << 7;
    const int bn   = blockIdx.x << 7;

    const int lr       = lane & 7;
    const int rowShift = ((lane >> 3) & 1) << 3;
    const int kShift   = (lane >> 4) << 2;

    float acc[4][4][4];
#pragma unroll
    for (int i = 0; i < 4; i++)
#pragma unroll
        for (int j = 0; j < 4; j++)
#pragma unroll
            for (int c = 0; c < 4; c++) acc[i][j][c] = 0.f;

    auto loadTiles = [&](int kb, int s) {
#pragma unroll
        for (int it = 0; it < 2; it++) {
            int f = tid + it * 256;
            int m = f >> 2, cq = f & 3;
            cp16(sA + ((s * 2560 + m * 20 + cq * 4) << 2),
                 &g_latb[(size_t)(bm + m) * ZZ + kb + cq * 8]);
        }
        int kb2 = kb >> 1;
#pragma unroll
        for (int it = 0; it < 2; it++) {
            int f = tid + it * 256;
            int k2 = f >> 5, nq = f & 31;
            cp16(sB + ((s * 2176 + k2 * 136 + nq * 4) << 2),
                 &g_W1[(size_t)(kb2 + k2) * CT + bn + nq * 4]);
        }
    };

    loadTiles(0, 0);
    CP_COMMIT();

    // absorbed: W -> g_W2 (bf16) while pipeline warms up
    {
        const int NW = (ZZ * CT) / 2;
        int flat = (blockIdx.y * gridDim.x + blockIdx.x) * 256 + tid;
        const int stride = gridDim.x * gridDim.y * 256;
        for (int p = flat; p < NW; p += stride) {
            float2 v = reinterpret_cast<const float2*>(W)[p];
            reinterpret_cast<__nv_bfloat162*>(g_W2)[p] = __floats2bfloat162_rn(v.x, v.y);
        }
    }

    const int NK = ZZ / 32;  // 8
    for (int kt = 0; kt < NK; kt++) {
        if (kt + 1 < NK) loadTiles((kt + 1) * 32, (kt + 1) & 1);
        CP_COMMIT();
        CP_WAIT1();
        __syncthreads();

        const uint32_t aStage = (kt & 1) * 2560;
        const uint32_t* bs = BsU + (kt & 1) * 2176;
#pragma unroll
        for (int ks = 0; ks < 2; ks++) {
            const int kc2 = ks * 8;
            uint32_t afr[4][4];
#pragma unroll
            for (int i = 0; i < 4; i++) {
                int r0b = wm * 64 + i * 16;
                uint32_t aw = aStage + (uint32_t)(r0b + lr + rowShift) * 20 + kc2 + kShift;
                ldsm_x4(afr[i], sA + (aw << 2));
            }
            uint32_t bfr[4][2];
#pragma unroll
            for (int j = 0; j < 4; j++) {
                int c0 = wn * 32 + j * 8 + g;
                bfr[j][0] = bs[(kc2 + tg) * 136 + c0];
                bfr[j][1] = bs[(kc2 + tg + 4) * 136 + c0];
            }
#pragma unroll
            for (int i = 0; i < 4; i++)
#pragma unroll
                for (int j = 0; j < 4; j++)
                    mma_bf16(acc[i][j][0], acc[i][j][1], acc[i][j][2], acc[i][j][3],
                             afr[i][0], afr[i][1], afr[i][2], afr[i][3],
                             bfr[j][0], bfr[j][1]);
        }
        __syncthreads();
    }

#pragma unroll
    for (int i = 0; i < 4; i++) {
#pragma unroll
        for (int j = 0; j < 4; j++) {
            int row0 = bm + wm * 64 + i * 16 + g;
            int col  = bn + wn * 32 + j * 8 + 2 * tg;
            {
                size_t o = (size_t)row0 * CT + col;
                float2 bv = *reinterpret_cast<const float2*>(&base[o]);
                *reinterpret_cast<__nv_bfloat162*>(&g_qsb[o]) =
                    __floats2bfloat162_rn(acc[i][j][0] + bv.x, acc[i][j][1] + bv.y);
            }
            {
                size_t o = (size_t)(row0 + 8) * CT + col;
                float2 bv = *reinterpret_cast<const float2*>(&base[o]);
                *reinterpret_cast<__nv_bfloat162*>(&g_qsb[o]) =
                    __floats2bfloat162_rn(acc[i][j][2] + bv.x, acc[i][j][3] + bv.y);
            }
        }
    }
}

// ---------------------------------------------------------------------------
// GEMM2 (bf16, cp.async 4-stage deep pipeline, split-K=32, ldmatrix frags)
__global__ __launch_bounds__(256, 2) void gemm2_tc()
{
    extern __shared__ uint32_t smem[];
    uint32_t* AsU = smem;                  // 4 * 2560
    uint32_t* WsU = smem + 10240;          // 4 * 2560
    const uint32_t sA = (uint32_t)__cvta_generic_to_shared(AsU);
    const uint32_t sW = (uint32_t)__cvta_generic_to_shared(WsU);

    const int tid  = threadIdx.x;
    const int lane = tid & 31;
    const int wid  = tid >> 5;
    const int wm   = wid & 1;
    const int wn   = wid >> 1;
    const int bm   = blockIdx.y << 7;
    const int bn   = blockIdx.x << 7;
    const int k0s  = blockIdx.z * (CT / 32);

    const int lr       = lane & 7;
    const int rowShift = ((lane >> 3) & 1) << 3;
    const int kShift   = (lane >> 4) << 2;
    const int selB     = ((lane >> 3) & 1) << 2;

    float acc[4][4][4];
#pragma unroll
    for (int i = 0; i < 4; i++)
#pragma unroll
        for (int j = 0; j < 4; j++)
#pragma unroll
            for (int c = 0; c < 4; c++) acc[i][j][c] = 0.f;

    auto loadTiles = [&](int kb, int s) {
#pragma unroll
        for (int it = 0; it < 2; it++) {
            int f = tid + it * 256;
            int m = f >> 2, cq = f & 3;
            cp16(sA + ((s * 2560 + m * 20 + cq * 4) << 2),
                 &g_dqsb[(size_t)(bm + m) * CT + kb + cq * 8]);
        }
#pragma unroll
        for (int it = 0; it < 2; it++) {
            int f = tid + it * 256;
            int z = f >> 2, cq = f & 3;
            cp16(sW + ((s * 2560 + z * 20 + cq * 4) << 2),
                 &g_W2[(size_t)(bn + z) * CT + kb + cq * 8]);
        }
    };

    loadTiles(k0s, 0);      CP_COMMIT();
    loadTiles(k0s + 32, 1); CP_COMMIT();
    loadTiles(k0s + 64, 2); CP_COMMIT();

    const int NK = (CT / 32) / 32;  // 12
    for (int kt = 0; kt < NK; kt++) {
        CP_WAIT2();
        __syncthreads();
        if (kt + 3 < NK) loadTiles(k0s + (kt + 3) * 32, (kt + 3) & 3);
        CP_COMMIT();

        const uint32_t base = (kt & 3) * 2560;
#pragma unroll
        for (int ks = 0; ks < 2; ks++) {
            const int kc2 = ks * 8;
            uint32_t afr[4][4];
#pragma unroll
            for (int i = 0; i < 4; i++) {
                int r0b = wm * 64 + i * 16;
                uint32_t aw = base + (uint32_t)(r0b + lr + rowShift) * 20 + kc2 + kShift;
                ldsm_x4(afr[i], sA + (aw << 2));
            }
            uint32_t bfr[4][2];
#pragma unroll
            for (int j = 0; j < 4; j++) {
                int c0b = wn * 32 + j * 8;
                uint32_t bw = base + (uint32_t)(c0b + lr) * 20 + kc2 + selB;
                ldsm_x2(bfr[j], sW + (bw << 2));
            }
#pragma unroll
            for (int i = 0; i < 4; i++)
#pragma unroll
                for (int j = 0; j < 4; j++)
                    mma_bf16(acc[i][j][0], acc[i][j][1], acc[i][j][2], acc[i][j][3],
                             afr[i][0], afr[i][1], afr[i][2], afr[i][3],
                             bfr[j][0], bfr[j][1]);
        }
    }

    const int g  = lane >> 2;
    const int tg = lane & 3;
#pragma unroll
    for (int i = 0; i < 4; i++)
#pragma unroll
        for (int j = 0; j < 4; j++) {
            int row0 = bm + wm * 64 + i * 16 + g;
            int col  = bn + wn * 32 + j * 8 + 2 * tg;
            atomicAdd(&g_grad[(size_t)row0 * ZZ + col],           acc[i][j][0]);
            atomicAdd(&g_grad[(size_t)row0 * ZZ + col + 1],       acc[i][j][1]);
            atomicAdd(&g_grad[(size_t)(row0 + 8) * ZZ + col],     acc[i][j][2]);
            atomicAdd(&g_grad[(size_t)(row0 + 8) * ZZ + col + 1], acc[i][j][3]);
        }
}

// ---------------------------------------------------------------------------
__device__ __forceinline__ void qrot(const float* __restrict__ q,
                                     const float* __restrict__ v,
                                     float* __restrict__ r)
{
    float w = q[0], x = q[1], y = q[2], z = q[3];
    float inv = 1.0f / (w * w + x * x + y * y + z * z);
    float a = w * w - (x * x + y * y + z * z);
    float d = 2.0f * (x * v[0] + y * v[1] + z * v[2]);
    float cx = y * v[2] - z * v[1];
    float cy = z * v[0] - x * v[2];
    float cz = x * v[1] - y * v[0];
    float tw = 2.0f * w;
    r[0] = (a * v[0] + d * x + tw * cx) * inv;
    r[1] = (a * v[1] + d * y + tw * cy) * inv;
    r[2] = (a * v[2] + d * z + tw * cz) * inv;
}

__device__ __forceinline__ void qrot_bwd(const float* __restrict__ q,
                                         const float* __restrict__ v,
                                         const float* __restrict__ g,
                                         float& dw, float& dx, float& dy, float& dz)
{
    float w = q[0], x = q[1], y = q[2], z = q[3];
    float inv = 1.0f / (w * w + x * x + y * y + z * z);
    float a = w * w - (x * x + y * y + z * z);
    float dd = 2.0f * (x * v[0] + y * v[1] + z * v[2]);
    float cx = y * v[2] - z * v[1];
    float cy = z * v[0] - x * v[2];
    float cz = x * v[1] - y * v[0];
    float tw = 2.0f * w;
    float r0 = (a * v[0] + dd * x + tw * cx) * inv;
    float r1 = (a * v[1] + dd * y + tw * cy) * inv;
    float r2 = (a * v[2] + dd * z + tw * cz) * inv;
    float c1 = v[0] * g[0] + v[1] * g[1] + v[2] * g[2];
    float c2 = x * g[0] + y * g[1] + z * g[2];
    float c3 = 0.5f * dd;
    float gr = g[0] * r0 + g[1] * r1 + g[2] * r2;
    float cg = cx * g[0] + cy * g[1] + cz * g[2];
    float s = 2.0f * inv;
    float vgx = v[1] * g[2] - v[2] * g[1];
    float vgy = v[2] * g[0] - v[0] * g[2];
    float vgz = v[0] * g[1] - v[1] * g[0];
    dw += s * (w * c1 + cg - w * gr);
    dx += s * (-c1 * x + c2 * v[0] + c3 * g[0] + w * vgx - gr * x);
    dy += s * (-c1 * y + c2 * v[1] + c3 * g[1] + w * vgy - gr * y);
    dz += s * (-c1 * z + c2 * v[2] + c3 * g[2] + w * vgz - gr * z);
}

// ---------------------------------------------------------------------------
// Pose kernel: k-split, pd in SMEM (69 rows x 256), qs read as bf16.
#define SPD(r) s_pd[((r) - 3) * 256]
__global__ __launch_bounds__(256, 3) void pose_kernel(const float* __restrict__ tgt,
                                                      const float* __restrict__ stdq,
                                                      const float* __restrict__ meanq,
                                                      const float* __restrict__ offs)
{
    extern __shared__ float s_pd[];          // 69*256 floats
    __shared__ float s_std[CC], s_mean[CC], s_off[JJ * 3];
    __shared__ float s_red[32];
    const int b  = blockIdx.x;
    const int t  = threadIdx.x;
    const int tk = t >> 7;
    const int tt = t & 127;
    if (t < CC) { s_std[t] = stdq[t]; s_mean[t] = meanq[t]; }
    if (t >= 128 && t < 128 + JJ * 3) s_off[t - 128] = offs[b * JJ * 3 + (t - 128)];
    __syncthreads();

    float accR = 0.f, accJ = 0.f, accF = 0.f;

    const __nv_bfloat16* dbase = g_qsb + (size_t)(b * 2 + tk) * CT + tt;
    const float* tbase = tgt + (size_t)(b * 2 + tk) * (2 * CT) + tt;

    {
#pragma unroll
        for (int i = 0; i < 4; i++) {
            float df = __bfloat162float(dbase[(size_t)i * TT]) - tbase[(size_t)i * TT];
            accR += df * df;
        }
        const int leaves[5] = { 10, 11, 15, 22, 23 };
#pragma unroll
        for (int e = 0; e < 5; e++) {
            int j = leaves[e];
#pragma unroll
            for (int i = 0; i < 4; i++) {
                float df = __bfloat162float(dbase[(size_t)(4 * j + i) * TT])
                         - tbase[(size_t)(8 * j + i) * TT];
                accJ += df * df;
            }
        }
    }

    {
        float qD[4], qT[4];
        float pDx, pDy, pDz, pTx, pTy, pTz;

        auto loadPair = [&](int j) {
#pragma unroll
            for (int i = 0; i < 4; i++) {
                int c = 4 * j + i;
                float d  = __bfloat162float(dbase[(size_t)c * TT]);
                float tr = tbase[(size_t)(8 * j + i) * TT];
                float df = d - tr;
                accJ += df * df;
                qD[i] = d * s_std[c] + s_mean[c];
                qT[i] = tr * s_std[c] + s_mean[c];
            }
        };
        auto step = [&](int j) {
            const float* v = s_off + 3 * j;
            float r[3];
            qrot(qD, v, r); pDx += r[0]; pDy += r[1]; pDz += r[2];
            qrot(qT, v, r); pTx += r[0]; pTy += r[1]; pTz += r[2];
            float dx = pDx - pTx, dy = pDy - pTy, dz = pDz - pTz;
            accF += dx * dx + dy * dy + dz * dz;
            (&SPD(3 * j + 0))[t] = pDx;
            (&SPD(3 * j + 1))[t] = pDy;
            (&SPD(3 * j + 2))[t] = pDz;
        };
        auto reset = [&]() {
            pDx = pDy = pDz = pTx = pTy = pTz = 0.f;
            qD[0] = 1.f; qD[1] = qD[2] = qD[3] = 0.f;
            qT[0] = 1.f; qT[1] = qT[2] = qT[3] = 0.f;
        };

        reset();
        step(1); loadPair(1); step(4); loadPair(4); step(7); loadPair(7); step(10);
        reset();
        step(2); loadPair(2); step(5); loadPair(5); step(8); loadPair(8); step(11);
        reset();
        step(3); loadPair(3); step(6); loadPair(6); step(9); loadPair(9);
        float sp[6] = { pDx, pDy, pDz, pTx, pTy, pTz };
        float sqD[4] = { qD[0], qD[1], qD[2], qD[3] };
        float sqT[4] = { qT[0], qT[1], qT[2], qT[3] };
        step(12); loadPair(12); step(15);
        pDx = sp[0]; pDy = sp[1]; pDz = sp[2]; pTx = sp[3]; pTy = sp[4]; pTz = sp[5];
        qD[0] = sqD[0]; qD[1] = sqD[1]; qD[2] = sqD[2]; qD[3] = sqD[3];
        qT[0] = sqT[0]; qT[1] = sqT[1]; qT[2] = sqT[2]; qT[3] = sqT[3];
        step(13); loadPair(13); step(16); loadPair(16); step(18); loadPair(18);
        step(20); loadPair(20); step(22);
        pDx = sp[0]; pDy = sp[1]; pDz = sp[2]; pTx = sp[3]; pTy = sp[4]; pTz = sp[5];
        qD[0] = sqD[0]; qD[1] = sqD[1]; qD[2] = sqD[2]; qD[3] = sqD[3];
        qT[0] = sqT[0]; qT[1] = sqT[1]; qT[2] = sqT[2]; qT[3] = sqT[3];
        step(14); loadPair(14); step(17); loadPair(17); step(19); loadPair(19);
        step(21); loadPair(21); step(23);
    }
    __syncthreads();

    if (tk == 0) {
#pragma unroll
        for (int r = 3; r < 72; r++) {
            float* row = &SPD(r);
            float v = row[tt];
            row[tt] = 2.f * (v - row[tt + 128]);
        }
        const int ch[20] = { 23,22,21,20,19,18,17,16,15,14,13,12,11,10,9,8,7,6,5,4 };
        const int pa[20] = { 21,20,19,18,17,16,14,13,12, 9, 9, 9, 8, 7, 6, 5, 4, 3, 2, 1 };
#pragma unroll
        for (int e = 0; e < 20; e++) {
            int cj = ch[e], pj = pa[e];
#pragma unroll
            for (int i = 0; i < 3; i++)
                (&SPD(3 * pj + i))[tt] += (&SPD(3 * cj + i))[tt];
        }
    }
    __syncthreads();

    __nv_bfloat16* outp = g_dqsb + (size_t)b * CT + tt;
    const __nv_bfloat16* dbase0 = g_qsb + (size_t)(b * 2) * CT + tt;
    auto doParent = [&](int p, int c0, int c1, int c2) {
        float q[4];
#pragma unroll
        for (int i = 0; i < 4; i++) {
            int c = 4 * p + i;
            q[i] = __bfloat162float(dbase0[(size_t)c * TT]) * s_std[c] + s_mean[c];
        }
        float dw = 0.f, dx = 0.f, dy = 0.f, dz = 0.f;
        float gv[3];
        gv[0] = (&SPD(3 * c0 + 0))[tt];
        gv[1] = (&SPD(3 * c0 + 1))[tt];
        gv[2] = (&SPD(3 * c0 + 2))[tt];
        qrot_bwd(q, s_off + 3 * c0, gv, dw, dx, dy, dz);
        if (c1 >= 0) {
            gv[0] = (&SPD(3 * c1 + 0))[tt];
            gv[1] = (&SPD(3 * c1 + 1))[tt];
            gv[2] = (&SPD(3 * c1 + 2))[tt];
            qrot_bwd(q, s_off + 3 * c1, gv, dw, dx, dy, dz);
        }
        if (c2 >= 0) {
            gv[0] = (&SPD(3 * c2 + 0))[tt];
            gv[1] = (&SPD(3 * c2 + 1))[tt];
            gv[2] = (&SPD(3 * c2 + 2))[tt];
            qrot_bwd(q, s_off + 3 * c2, gv, dw, dx, dy, dz);
        }
        outp[(size_t)(4 * p + 0) * TT] = __float2bfloat16_rn(dw * s_std[4 * p + 0]);
        outp[(size_t)(4 * p + 1) * TT] = __float2bfloat16_rn(dx * s_std[4 * p + 1]);
        outp[(size_t)(4 * p + 2) * TT] = __float2bfloat16_rn(dy * s_std[4 * p + 2]);
        outp[(size_t)(4 * p + 3) * TT] = __float2bfloat16_rn(dz * s_std[4 * p + 3]);
    };
    const __nv_bfloat16 bz = __float2bfloat16_rn(0.f);
    if (tk == 0) {
        const int zj[3] = { 0, 10, 11 };
#pragma unroll
        for (int e = 0; e < 3; e++)
#pragma unroll
            for (int i = 0; i < 4; i++)
                outp[(size_t)(4 * zj[e] + i) * TT] = bz;
        doParent(1, 4, -1, -1);  doParent(2, 5, -1, -1);  doParent(3, 6, -1, -1);
        doParent(4, 7, -1, -1);  doParent(5, 8, -1, -1);  doParent(6, 9, -1, -1);
        doParent(7, 10, -1, -1); doParent(8, 11, -1, -1);
        doParent(9, 12, 13, 14);
    } else {
        const int zj[3] = { 15, 22, 23 };
#pragma unroll
        for (int e = 0; e < 3; e++)
#pragma unroll
            for (int i = 0; i < 4; i++)
                outp[(size_t)(4 * zj[e] + i) * TT] = bz;
        doParent(12, 15, -1, -1); doParent(13, 16, -1, -1); doParent(14, 17, -1, -1);
        doParent(16, 18, -1, -1); doParent(17, 19, -1, -1); doParent(18, 20, -1, -1);
        doParent(19, 21, -1, -1); doParent(20, 22, -1, -1); doParent(21, 23, -1, -1);
    }

    float r = blockReduce(accR, s_red);
    if (threadIdx.x == 0) atomicAdd(&g_acc[0], (double)r);
    __syncthreads();
    r = blockReduce(accJ, s_red);
    if (threadIdx.x == 0) atomicAdd(&g_acc[1], (double)r);
    __syncthreads();
    r = blockReduce(accF, s_red);
    if (threadIdx.x == 0) atomicAdd(&g_acc[2], (double)r);
}

// ---------------------------------------------------------------------------
// cons loss only; last arriving block finalizes the output.
__global__ void cons_kernel(const float* __restrict__ lat, float* __restrict__ out)
{
    __shared__ float s_red[32];
    int i = blockIdx.x * blockDim.x + threadIdx.x;
    int b = i >> 8, z = i & 255;
    float d = lat[(size_t)(2 * b) * ZZ + z] - g_grad[i] - lat[(size_t)(2 * b + 1) * ZZ + z];
    float r = blockReduce(d * d, s_red);
    if (threadIdx.x == 0) atomicAdd(&g_acc[5], (double)r);

    if (threadIdx.x == 0) {
        __threadfence();
        unsigned int c = atomicAdd(&g_cnt, 1u);
        if (c == gridDim.x - 1) {
            out[0] = (float)(-0.5 * g_acc[3] / 1024.0) * 0.001f;
            out[1] = (float)(g_acc[0] / 524288.0);
            out[2] = (float)(g_acc[4] / 393216.0);
            out[3] = (float)(g_acc[5] / 131072.0) * 0.1f;
            out[4] = (float)(g_acc[2] / 9437184.0) * 0.1f;
            out[5] = (float)(g_acc[1] / 12058624.0);
        }
    }
}

// ---------------------------------------------------------------------------
extern "C" void kernel_launch(void* const* d_in, const int* in_sizes, int n_in,
                              void* d_out, int out_size)
{
    const float* base  = (const float*)d_in[0];
    const float* tgt   = (const float*)d_in[1];
    const float* idisp = (const float*)d_in[2];
    const float* tdisp = (const float*)d_in[3];
    const float* mu    = (const float*)d_in[4];
    const float* lv    = (const float*)d_in[5];
    const float* lat   = (const float*)d_in[6];
    const float* W     = (const float*)d_in[7];
    const float* meanq = (const float*)d_in[8];
    const float* stdq  = (const float*)d_in[9];
    const float* offs  = (const float*)d_in[10];
    float* out = (float*)d_out;

    cudaFuncSetAttribute(gemm1_tc, cudaFuncAttributeMaxDynamicSharedMemorySize, 37888);
    cudaFuncSetAttribute(gemm2_tc, cudaFuncAttributeMaxDynamicSharedMemorySize, 81920);
    cudaFuncSetAttribute(pose_kernel, cudaFuncAttributeMaxDynamicSharedMemorySize, 70656);

    cvt_kernel<<<6657, 256>>>(W, lat, idisp, tdisp, mu, lv);
    gemm1_tc<<<dim3(96, 8), 256, 37888>>>(base, W);
    pose_kernel<<<BP, 256, 70656>>>(tgt, stdq, meanq, offs);
    gemm2_tc<<<dim3(2, 4, 32), 256, 81920>>>();
    cons_kernel<<<512, 256>>>(lat, out);
}

// round 15
// speedup vs baseline: 1.0161x; 1.0161x over previous
#include <cuda_runtime.h>
#include <cuda_bf16.h>
#include <cstdint>

#define BP 512
#define CC 96
#define TT 128
#define JJ 24
#define ZZ 256
#define CT 12288
#define N2 1024

__device__ __nv_bfloat16  g_qsb[(size_t)N2 * CT];    // decoded motion bf16
__device__ __nv_bfloat16  g_dqsb[(size_t)BP * CT];   // d f / d qs (bf16)
__device__ float          g_grad[(size_t)BP * ZZ];   // grad wrt latent[:,0]
__device__ double         g_acc[6];                  // root joints fk kld disp cons
__device__ unsigned int   g_cnt;                     // cons arrival counter
__device__ __nv_bfloat16  g_W2[(size_t)ZZ * CT];     // W bf16, [z][ct] (filled by gemm1)
__device__ uint32_t       g_W1[(size_t)(ZZ / 2) * CT]; // W bf16 k-pair packed [k2][n]
__device__ __nv_bfloat16  g_latb[(size_t)N2 * ZZ];   // latent bf16

// ---------------------------------------------------------------------------
// cvt: W1 (k-pair packed) + latent -> bf16, plus zero-init. (~13 MB traffic)
__global__ void cvt_kernel(const float* __restrict__ W, const float* __restrict__ lat)
{
    const int NW1 = (ZZ / 2) * CT;       // 1572864
    const int NL  = (N2 * ZZ) / 2;       // 131072
    int i = blockIdx.x * blockDim.x + threadIdx.x;
    if (i < BP * ZZ) g_grad[i] = 0.f;
    if (i < 6)       g_acc[i] = 0.0;
    if (i == 6)      g_cnt = 0u;
    if (i < NW1) {
        int k2 = i / CT, n = i - k2 * CT;
        float lo = W[(size_t)(2 * k2) * CT + n];
        float hi = W[(size_t)(2 * k2 + 1) * CT + n];
        __nv_bfloat162 h = __floats2bfloat162_rn(lo, hi);
        g_W1[i] = *reinterpret_cast<uint32_t*>(&h);
    } else if (i < NW1 + NL) {
        int j = i - NW1;
        float2 v = reinterpret_cast<const float2*>(lat)[j];
        reinterpret_cast<__nv_bfloat162*>(g_latb)[j] = __floats2bfloat162_rn(v.x, v.y);
    }
}

// ---------------------------------------------------------------------------
__device__ __forceinline__ float blockReduce(float v, float* sm) {
#pragma unroll
    for (int o = 16; o > 0; o >>= 1) v += __shfl_down_sync(0xffffffffu, v, o);
    int lane = threadIdx.x & 31, w = threadIdx.x >> 5;
    if (lane == 0) sm[w] = v;
    __syncthreads();
    v = 0.f;
    if (threadIdx.x < 32) {
        int nw = (blockDim.x + 31) >> 5;
        v = (threadIdx.x < nw) ? sm[threadIdx.x] : 0.f;
#pragma unroll
        for (int o = 16; o > 0; o >>= 1) v += __shfl_down_sync(0xffffffffu, v, o);
    }
    return v;
}

// ---------------------------------------------------------------------------
__device__ __forceinline__ void cp16(uint32_t dst, const void* src) {
    asm volatile("cp.async.ca.shared.global [%0], [%1], 16;\n" :: "r"(dst), "l"(src));
}
#define CP_COMMIT() asm volatile("cp.async.commit_group;\n")
#define CP_WAIT1()  asm volatile("cp.async.wait_group 1;\n")

__device__ __forceinline__ void mma_bf16(float& c0, float& c1, float& c2, float& c3,
                                         uint32_t a0, uint32_t a1, uint32_t a2, uint32_t a3,
                                         uint32_t b0, uint32_t b1)
{
    asm volatile("mma.sync.aligned.m16n8k16.row.col.f32.bf16.bf16.f32 "
                 "{%0,%1,%2,%3}, {%4,%5,%6,%7}, {%8,%9}, {%0,%1,%2,%3};"
                 : "+f"(c0), "+f"(c1), "+f"(c2), "+f"(c3)
                 : "r"(a0), "r"(a1), "r"(a2), "r"(a3), "r"(b0), "r"(b1));
}

__device__ __forceinline__ void ldsm_x4(uint32_t* r, uint32_t addr) {
    asm volatile("ldmatrix.sync.aligned.m8n8.x4.shared.b16 {%0,%1,%2,%3}, [%4];"
                 : "=r"(r[0]), "=r"(r[1]), "=r"(r[2]), "=r"(r[3]) : "r"(addr));
}
__device__ __forceinline__ void ldsm_x2(uint32_t* r, uint32_t addr) {
    asm volatile("ldmatrix.sync.aligned.m8n8.x2.shared.b16 {%0,%1}, [%2];"
                 : "=r"(r[0]), "=r"(r[1]) : "r"(addr));
}

// ---------------------------------------------------------------------------
// GEMM1 (bf16 m16n8k16, cp.async 2-stage, A-frags via ldmatrix):
// g_qsb = latb(1024x256)@W1 + base. Also converts W -> g_W2 (for gemm2).
__global__ __launch_bounds__(256, 2) void gemm1_tc(const float* __restrict__ base,
                                                   const float* __restrict__ W)
{
    extern __shared__ uint32_t smem[];
    uint32_t* AsU = smem;                 // 2 * 2560
    uint32_t* BsU = smem + 5120;          // 2 * 2176
    const uint32_t sA = (uint32_t)__cvta_generic_to_shared(AsU);
    const uint32_t sB = (uint32_t)__cvta_generic_to_shared(BsU);

    const int tid  = threadIdx.x;
    const int lane = tid & 31;
    const int wid  = tid >> 5;
    const int wm   = wid & 1;
    const int wn   = wid >> 1;
    const int g    = lane >> 2;
    const int tg   = lane & 3;
    const int bm   = blockIdx.y << 7;
    const int bn   = blockIdx.x << 7;

    const int lr       = lane & 7;
    const int rowShift = ((lane >> 3) & 1) << 3;
    const int kShift   = (lane >> 4) << 2;

    float acc[4][4][4];
#pragma unroll
    for (int i = 0; i < 4; i++)
#pragma unroll
        for (int j = 0; j < 4; j++)
#pragma unroll
            for (int c = 0; c < 4; c++) acc[i][j][c] = 0.f;

    auto loadTiles = [&](int kb, int s) {
#pragma unroll
        for (int it = 0; it < 2; it++) {
            int f = tid + it * 256;
            int m = f >> 2, cq = f & 3;
            cp16(sA + ((s * 2560 + m * 20 + cq * 4) << 2),
                 &g_latb[(size_t)(bm + m) * ZZ + kb + cq * 8]);
        }
        int kb2 = kb >> 1;
#pragma unroll
        for (int it = 0; it < 2; it++) {
            int f = tid + it * 256;
            int k2 = f >> 5, nq = f & 31;
            cp16(sB + ((s * 2176 + k2 * 136 + nq * 4) << 2),
                 &g_W1[(size_t)(kb2 + k2) * CT + bn + nq * 4]);
        }
    };

    loadTiles(0, 0);
    CP_COMMIT();

    // absorbed: W -> g_W2 (bf16) while pipeline warms up
    {
        const int NW = (ZZ * CT) / 2;
        int flat = (blockIdx.y * gridDim.x + blockIdx.x) * 256 + tid;
        const int stride = gridDim.x * gridDim.y * 256;
        for (int p = flat; p < NW; p += stride) {
            float2 v = reinterpret_cast<const float2*>(W)[p];
            reinterpret_cast<__nv_bfloat162*>(g_W2)[p] = __floats2bfloat162_rn(v.x, v.y);
        }
    }

    const int NK = ZZ / 32;  // 8
    for (int kt = 0; kt < NK; kt++) {
        if (kt + 1 < NK) loadTiles((kt + 1) * 32, (kt + 1) & 1);
        CP_COMMIT();
        CP_WAIT1();
        __syncthreads();

        const uint32_t aStage = (kt & 1) * 2560;
        const uint32_t* bs = BsU + (kt & 1) * 2176;
#pragma unroll
        for (int ks = 0; ks < 2; ks++) {
            const int kc2 = ks * 8;
            uint32_t afr[4][4];
#pragma unroll
            for (int i = 0; i < 4; i++) {
                int r0b = wm * 64 + i * 16;
                uint32_t aw = aStage + (uint32_t)(r0b + lr + rowShift) * 20 + kc2 + kShift;
                ldsm_x4(afr[i], sA + (aw << 2));
            }
            uint32_t bfr[4][2];
#pragma unroll
            for (int j = 0; j < 4; j++) {
                int c0 = wn * 32 + j * 8 + g;
                bfr[j][0] = bs[(kc2 + tg) * 136 + c0];
                bfr[j][1] = bs[(kc2 + tg + 4) * 136 + c0];
            }
#pragma unroll
            for (int i = 0; i < 4; i++)
#pragma unroll
                for (int j = 0; j < 4; j++)
                    mma_bf16(acc[i][j][0], acc[i][j][1], acc[i][j][2], acc[i][j][3],
                             afr[i][0], afr[i][1], afr[i][2], afr[i][3],
                             bfr[j][0], bfr[j][1]);
        }
        __syncthreads();
    }

#pragma unroll
    for (int i = 0; i < 4; i++) {
#pragma unroll
        for (int j = 0; j < 4; j++) {
            int row0 = bm + wm * 64 + i * 16 + g;
            int col  = bn + wn * 32 + j * 8 + 2 * tg;
            {
                size_t o = (size_t)row0 * CT + col;
                float2 bv = *reinterpret_cast<const float2*>(&base[o]);
                *reinterpret_cast<__nv_bfloat162*>(&g_qsb[o]) =
                    __floats2bfloat162_rn(acc[i][j][0] + bv.x, acc[i][j][1] + bv.y);
            }
            {
                size_t o = (size_t)(row0 + 8) * CT + col;
                float2 bv = *reinterpret_cast<const float2*>(&base[o]);
                *reinterpret_cast<__nv_bfloat162*>(&g_qsb[o]) =
                    __floats2bfloat162_rn(acc[i][j][2] + bv.x, acc[i][j][3] + bv.y);
            }
        }
    }
}

// ---------------------------------------------------------------------------
// GEMM2 (bf16, cp.async 3-stage, split-K=32, ldmatrix fragments) — pure.
__global__ __launch_bounds__(256, 2) void gemm2_tc()
{
    extern __shared__ uint32_t smem[];
    uint32_t* AsU = smem;                 // 3 * 2560
    uint32_t* WsU = smem + 7680;          // 3 * 2560
    const uint32_t sA = (uint32_t)__cvta_generic_to_shared(AsU);
    const uint32_t sW = (uint32_t)__cvta_generic_to_shared(WsU);

    const int tid  = threadIdx.x;
    const int lane = tid & 31;
    const int wid  = tid >> 5;
    const int wm   = wid & 1;
    const int wn   = wid >> 1;
    const int bm   = blockIdx.y << 7;
    const int bn   = blockIdx.x << 7;
    const int k0s  = blockIdx.z * (CT / 32);

    const int lr       = lane & 7;
    const int rowShift = ((lane >> 3) & 1) << 3;
    const int kShift   = (lane >> 4) << 2;
    const int selB     = ((lane >> 3) & 1) << 2;

    float acc[4][4][4];
#pragma unroll
    for (int i = 0; i < 4; i++)
#pragma unroll
        for (int j = 0; j < 4; j++)
#pragma unroll
            for (int c = 0; c < 4; c++) acc[i][j][c] = 0.f;

    auto loadTiles = [&](int kb, int s) {
#pragma unroll
        for (int it = 0; it < 2; it++) {
            int f = tid + it * 256;
            int m = f >> 2, cq = f & 3;
            cp16(sA + ((s * 2560 + m * 20 + cq * 4) << 2),
                 &g_dqsb[(size_t)(bm + m) * CT + kb + cq * 8]);
        }
#pragma unroll
        for (int it = 0; it < 2; it++) {
            int f = tid + it * 256;
            int z = f >> 2, cq = f & 3;
            cp16(sW + ((s * 2560 + z * 20 + cq * 4) << 2),
                 &g_W2[(size_t)(bn + z) * CT + kb + cq * 8]);
        }
    };

    loadTiles(k0s, 0);      CP_COMMIT();
    loadTiles(k0s + 32, 1); CP_COMMIT();

    const int NK = (CT / 32) / 32;  // 12
    int stage = 0;
    int lstage = 2;
    for (int kt = 0; kt < NK; kt++) {
        CP_WAIT1();
        __syncthreads();
        if (kt + 2 < NK) {
            loadTiles(k0s + (kt + 2) * 32, lstage);
            if (++lstage == 3) lstage = 0;
        }
        CP_COMMIT();

        const uint32_t base = stage * 2560;
        if (++stage == 3) stage = 0;
#pragma unroll
        for (int ks = 0; ks < 2; ks++) {
            const int kc2 = ks * 8;
            uint32_t afr[4][4];
#pragma unroll
            for (int i = 0; i < 4; i++) {
                int r0b = wm * 64 + i * 16;
                uint32_t aw = base + (uint32_t)(r0b + lr + rowShift) * 20 + kc2 + kShift;
                ldsm_x4(afr[i], sA + (aw << 2));
            }
            uint32_t bfr[4][2];
#pragma unroll
            for (int j = 0; j < 4; j++) {
                int c0b = wn * 32 + j * 8;
                uint32_t bw = base + (uint32_t)(c0b + lr) * 20 + kc2 + selB;
                ldsm_x2(bfr[j], sW + (bw << 2));
            }
#pragma unroll
            for (int i = 0; i < 4; i++)
#pragma unroll
                for (int j = 0; j < 4; j++)
                    mma_bf16(acc[i][j][0], acc[i][j][1], acc[i][j][2], acc[i][j][3],
                             afr[i][0], afr[i][1], afr[i][2], afr[i][3],
                             bfr[j][0], bfr[j][1]);
        }
    }

    const int g  = lane >> 2;
    const int tg = lane & 3;
#pragma unroll
    for (int i = 0; i < 4; i++)
#pragma unroll
        for (int j = 0; j < 4; j++) {
            int row0 = bm + wm * 64 + i * 16 + g;
            int col  = bn + wn * 32 + j * 8 + 2 * tg;
            atomicAdd(&g_grad[(size_t)row0 * ZZ + col],           acc[i][j][0]);
            atomicAdd(&g_grad[(size_t)row0 * ZZ + col + 1],       acc[i][j][1]);
            atomicAdd(&g_grad[(size_t)(row0 + 8) * ZZ + col],     acc[i][j][2]);
            atomicAdd(&g_grad[(size_t)(row0 + 8) * ZZ + col + 1], acc[i][j][3]);
        }
}

// ---------------------------------------------------------------------------
__device__ __forceinline__ void qrot(const float* __restrict__ q,
                                     const float* __restrict__ v,
                                     float* __restrict__ r)
{
    float w = q[0], x = q[1], y = q[2], z = q[3];
    float inv = 1.0f / (w * w + x * x + y * y + z * z);
    float a = w * w - (x * x + y * y + z * z);
    float d = 2.0f * (x * v[0] + y * v[1] + z * v[2]);
    float cx = y * v[2] - z * v[1];
    float cy = z * v[0] - x * v[2];
    float cz = x * v[1] - y * v[0];
    float tw = 2.0f * w;
    r[0] = (a * v[0] + d * x + tw * cx) * inv;
    r[1] = (a * v[1] + d * y + tw * cy) * inv;
    r[2] = (a * v[2] + d * z + tw * cz) * inv;
}

__device__ __forceinline__ void qrot_bwd(const float* __restrict__ q,
                                         const float* __restrict__ v,
                                         const float* __restrict__ g,
                                         float& dw, float& dx, float& dy, float& dz)
{
    float w = q[0], x = q[1], y = q[2], z = q[3];
    float inv = 1.0f / (w * w + x * x + y * y + z * z);
    float a = w * w - (x * x + y * y + z * z);
    float dd = 2.0f * (x * v[0] + y * v[1] + z * v[2]);
    float cx = y * v[2] - z * v[1];
    float cy = z * v[0] - x * v[2];
    float cz = x * v[1] - y * v[0];
    float tw = 2.0f * w;
    float r0 = (a * v[0] + dd * x + tw * cx) * inv;
    float r1 = (a * v[1] + dd * y + tw * cy) * inv;
    float r2 = (a * v[2] + dd * z + tw * cz) * inv;
    float c1 = v[0] * g[0] + v[1] * g[1] + v[2] * g[2];
    float c2 = x * g[0] + y * g[1] + z * g[2];
    float c3 = 0.5f * dd;
    float gr = g[0] * r0 + g[1] * r1 + g[2] * r2;
    float cg = cx * g[0] + cy * g[1] + cz * g[2];
    float s = 2.0f * inv;
    float vgx = v[1] * g[2] - v[2] * g[1];
    float vgy = v[2] * g[0] - v[0] * g[2];
    float vgz = v[0] * g[1] - v[1] * g[0];
    dw += s * (w * c1 + cg - w * gr);
    dx += s * (-c1 * x + c2 * v[0] + c3 * g[0] + w * vgx - gr * x);
    dy += s * (-c1 * y + c2 * v[1] + c3 * g[1] + w * vgy - gr * y);
    dz += s * (-c1 * z + c2 * v[2] + c3 * g[2] + w * vgz - gr * z);
}

// ---------------------------------------------------------------------------
// Pose kernel: k-split, pd in SMEM (69 rows x 256), qs read as bf16.
// Absorbs the disp-MSE + KLD reductions (streaming loads hidden by FK latency).
#define SPD(r) s_pd[((r) - 3) * 256]
__global__ __launch_bounds__(256, 3) void pose_kernel(const float* __restrict__ tgt,
                                                      const float* __restrict__ stdq,
                                                      const float* __restrict__ meanq,
                                                      const float* __restrict__ offs,
                                                      const float* __restrict__ id,
                                                      const float* __restrict__ td,
                                                      const float* __restrict__ mu,
                                                      const float* __restrict__ lv)
{
    extern __shared__ float s_pd[];          // 69*256 floats
    __shared__ float s_std[CC], s_mean[CC], s_off[JJ * 3];
    __shared__ float s_red[32];
    const int b  = blockIdx.x;
    const int t  = threadIdx.x;
    const int tk = t >> 7;
    const int tt = t & 127;
    if (t < CC) { s_std[t] = stdq[t]; s_mean[t] = meanq[t]; }
    if (t >= 128 && t < 128 + JJ * 3) s_off[t - 128] = offs[b * JJ * 3 + (t - 128)];
    __syncthreads();

    // ---- absorbed disp/KLD (few elements per thread; overlap FK latency) ----
    float sd = 0.f, sk = 0.f;
    {
        int gi = b * 256 + t;
        const int gs = BP * 256;   // 131072
        for (int k = gi; k < BP * 2 * 3 * TT; k += gs) {
            float df = id[k] - td[k]; sd += df * df;
        }
        for (int k = gi; k < N2 * ZZ; k += gs) {
            float m = mu[k], l = lv[k];
            sk += 1.0f + l - m * m - expf(l);
        }
    }

    float accR = 0.f, accJ = 0.f, accF = 0.f;

    const __nv_bfloat16* dbase = g_qsb + (size_t)(b * 2 + tk) * CT + tt;
    const float* tbase = tgt + (size_t)(b * 2 + tk) * (2 * CT) + tt;

    {
#pragma unroll
        for (int i = 0; i < 4; i++) {
            float df = __bfloat162float(dbase[(size_t)i * TT]) - tbase[(size_t)i * TT];
            accR += df * df;
        }
        const int leaves[5] = { 10, 11, 15, 22, 23 };
#pragma unroll
        for (int e = 0; e < 5; e++) {
            int j = leaves[e];
#pragma unroll
            for (int i = 0; i < 4; i++) {
                float df = __bfloat162float(dbase[(size_t)(4 * j + i) * TT])
                         - tbase[(size_t)(8 * j + i) * TT];
                accJ += df * df;
            }
        }
    }

    {
        float qD[4], qT[4];
        float pDx, pDy, pDz, pTx, pTy, pTz;

        auto loadPair = [&](int j) {
#pragma unroll
            for (int i = 0; i < 4; i++) {
                int c = 4 * j + i;
                float d  = __bfloat162float(dbase[(size_t)c * TT]);
                float tr = tbase[(size_t)(8 * j + i) * TT];
                float df = d - tr;
                accJ += df * df;
                qD[i] = d * s_std[c] + s_mean[c];
                qT[i] = tr * s_std[c] + s_mean[c];
            }
        };
        auto step = [&](int j) {
            const float* v = s_off + 3 * j;
            float r[3];
            qrot(qD, v, r); pDx += r[0]; pDy += r[1]; pDz += r[2];
            qrot(qT, v, r); pTx += r[0]; pTy += r[1]; pTz += r[2];
            float dx = pDx - pTx, dy = pDy - pTy, dz = pDz - pTz;
            accF += dx * dx + dy * dy + dz * dz;
            (&SPD(3 * j + 0))[t] = pDx;
            (&SPD(3 * j + 1))[t] = pDy;
            (&SPD(3 * j + 2))[t] = pDz;
        };
        auto reset = [&]() {
            pDx = pDy = pDz = pTx = pTy = pTz = 0.f;
            qD[0] = 1.f; qD[1] = qD[2] = qD[3] = 0.f;
            qT[0] = 1.f; qT[1] = qT[2] = qT[3] = 0.f;
        };

        reset();
        step(1); loadPair(1); step(4); loadPair(4); step(7); loadPair(7); step(10);
        reset();
        step(2); loadPair(2); step(5); loadPair(5); step(8); loadPair(8); step(11);
        reset();
        step(3); loadPair(3); step(6); loadPair(6); step(9); loadPair(9);
        float sp[6] = { pDx, pDy, pDz, pTx, pTy, pTz };
        float sqD[4] = { qD[0], qD[1], qD[2], qD[3] };
        float sqT[4] = { qT[0], qT[1], qT[2], qT[3] };
        step(12); loadPair(12); step(15);
        pDx = sp[0]; pDy = sp[1]; pDz = sp[2]; pTx = sp[3]; pTy = sp[4]; pTz = sp[5];
        qD[0] = sqD[0]; qD[1] = sqD[1]; qD[2] = sqD[2]; qD[3] = sqD[3];
        qT[0] = sqT[0]; qT[1] = sqT[1]; qT[2] = sqT[2]; qT[3] = sqT[3];
        step(13); loadPair(13); step(16); loadPair(16); step(18); loadPair(18);
        step(20); loadPair(20); step(22);
        pDx = sp[0]; pDy = sp[1]; pDz = sp[2]; pTx = sp[3]; pTy = sp[4]; pTz = sp[5];
        qD[0] = sqD[0]; qD[1] = sqD[1]; qD[2] = sqD[2]; qD[3] = sqD[3];
        qT[0] = sqT[0]; qT[1] = sqT[1]; qT[2] = sqT[2]; qT[3] = sqT[3];
        step(14); loadPair(14); step(17); loadPair(17); step(19); loadPair(19);
        step(21); loadPair(21); step(23);
    }
    __syncthreads();

    if (tk == 0) {
#pragma unroll
        for (int r = 3; r < 72; r++) {
            float* row = &SPD(r);
            float v = row[tt];
            row[tt] = 2.f * (v - row[tt + 128]);
        }
        const int ch[20] = { 23,22,21,20,19,18,17,16,15,14,13,12,11,10,9,8,7,6,5,4 };
        const int pa[20] = { 21,20,19,18,17,16,14,13,12, 9, 9, 9, 8, 7, 6, 5, 4, 3, 2, 1 };
#pragma unroll
        for (int e = 0; e < 20; e++) {
            int cj = ch[e], pj = pa[e];
#pragma unroll
            for (int i = 0; i < 3; i++)
                (&SPD(3 * pj + i))[tt] += (&SPD(3 * cj + i))[tt];
        }
    }
    __syncthreads();

    __nv_bfloat16* outp = g_dqsb + (size_t)b * CT + tt;
    const __nv_bfloat16* dbase0 = g_qsb + (size_t)(b * 2) * CT + tt;
    auto doParent = [&](int p, int c0, int c1, int c2) {
        float q[4];
#pragma unroll
        for (int i = 0; i < 4; i++) {
            int c = 4 * p + i;
            q[i] = __bfloat162float(dbase0[(size_t)c * TT]) * s_std[c] + s_mean[c];
        }
        float dw = 0.f, dx = 0.f, dy = 0.f, dz = 0.f;
        float gv[3];
        gv[0] = (&SPD(3 * c0 + 0))[tt];
        gv[1] = (&SPD(3 * c0 + 1))[tt];
        gv[2] = (&SPD(3 * c0 + 2))[tt];
        qrot_bwd(q, s_off + 3 * c0, gv, dw, dx, dy, dz);
        if (c1 >= 0) {
            gv[0] = (&SPD(3 * c1 + 0))[tt];
            gv[1] = (&SPD(3 * c1 + 1))[tt];
            gv[2] = (&SPD(3 * c1 + 2))[tt];
            qrot_bwd(q, s_off + 3 * c1, gv, dw, dx, dy, dz);
        }
        if (c2 >= 0) {
            gv[0] = (&SPD(3 * c2 + 0))[tt];
            gv[1] = (&SPD(3 * c2 + 1))[tt];
            gv[2] = (&SPD(3 * c2 + 2))[tt];
            qrot_bwd(q, s_off + 3 * c2, gv, dw, dx, dy, dz);
        }
        outp[(size_t)(4 * p + 0) * TT] = __float2bfloat16_rn(dw * s_std[4 * p + 0]);
        outp[(size_t)(4 * p + 1) * TT] = __float2bfloat16_rn(dx * s_std[4 * p + 1]);
        outp[(size_t)(4 * p + 2) * TT] = __float2bfloat16_rn(dy * s_std[4 * p + 2]);
        outp[(size_t)(4 * p + 3) * TT] = __float2bfloat16_rn(dz * s_std[4 * p + 3]);
    };
    const __nv_bfloat16 bz = __float2bfloat16_rn(0.f);
    if (tk == 0) {
        const int zj[3] = { 0, 10, 11 };
#pragma unroll
        for (int e = 0; e < 3; e++)
#pragma unroll
            for (int i = 0; i < 4; i++)
                outp[(size_t)(4 * zj[e] + i) * TT] = bz;
        doParent(1, 4, -1, -1);  doParent(2, 5, -1, -1);  doParent(3, 6, -1, -1);
        doParent(4, 7, -1, -1);  doParent(5, 8, -1, -1);  doParent(6, 9, -1, -1);
        doParent(7, 10, -1, -1); doParent(8, 11, -1, -1);
        doParent(9, 12, 13, 14);
    } else {
        const int zj[3] = { 15, 22, 23 };
#pragma unroll
        for (int e = 0; e < 3; e++)
#pragma unroll
            for (int i = 0; i < 4; i++)
                outp[(size_t)(4 * zj[e] + i) * TT] = bz;
        doParent(12, 15, -1, -1); doParent(13, 16, -1, -1); doParent(14, 17, -1, -1);
        doParent(16, 18, -1, -1); doParent(17, 19, -1, -1); doParent(18, 20, -1, -1);
        doParent(19, 21, -1, -1); doParent(20, 22, -1, -1); doParent(21, 23, -1, -1);
    }

    float r = blockReduce(accR, s_red);
    if (threadIdx.x == 0) atomicAdd(&g_acc[0], (double)r);
    __syncthreads();
    r = blockReduce(accJ, s_red);
    if (threadIdx.x == 0) atomicAdd(&g_acc[1], (double)r);
    __syncthreads();
    r = blockReduce(accF, s_red);
    if (threadIdx.x == 0) atomicAdd(&g_acc[2], (double)r);
    __syncthreads();
    r = blockReduce(sd, s_red);
    if (threadIdx.x == 0) atomicAdd(&g_acc[4], (double)r);
    __syncthreads();
    r = blockReduce(sk, s_red);
    if (threadIdx.x == 0) atomicAdd(&g_acc[3], (double)r);
}

// ---------------------------------------------------------------------------
// cons loss only; last arriving block finalizes the output.
__global__ void cons_kernel(const float* __restrict__ lat, float* __restrict__ out)
{
    __shared__ float s_red[32];
    int i = blockIdx.x * blockDim.x + threadIdx.x;
    int b = i >> 8, z = i & 255;
    float d = lat[(size_t)(2 * b) * ZZ + z] - g_grad[i] - lat[(size_t)(2 * b + 1) * ZZ + z];
    float r = blockReduce(d * d, s_red);
    if (threadIdx.x == 0) atomicAdd(&g_acc[5], (double)r);

    if (threadIdx.x == 0) {
        __threadfence();
        unsigned int c = atomicAdd(&g_cnt, 1u);
        if (c == gridDim.x - 1) {
            out[0] = (float)(-0.5 * g_acc[3] / 1024.0) * 0.001f;
            out[1] = (float)(g_acc[0] / 524288.0);
            out[2] = (float)(g_acc[4] / 393216.0);
            out[3] = (float)(g_acc[5] / 131072.0) * 0.1f;
            out[4] = (float)(g_acc[2] / 9437184.0) * 0.1f;
            out[5] = (float)(g_acc[1] / 12058624.0);
        }
    }
}

// ---------------------------------------------------------------------------
extern "C" void kernel_launch(void* const* d_in, const int* in_sizes, int n_in,
                              void* d_out, int out_size)
{
    const float* base  = (const float*)d_in[0];
    const float* tgt   = (const float*)d_in[1];
    const float* idisp = (const float*)d_in[2];
    const float* tdisp = (const float*)d_in[3];
    const float* mu    = (const float*)d_in[4];
    const float* lv    = (const float*)d_in[5];
    const float* lat   = (const float*)d_in[6];
    const float* W     = (const float*)d_in[7];
    const float* meanq = (const float*)d_in[8];
    const float* stdq  = (const float*)d_in[9];
    const float* offs  = (const float*)d_in[10];
    float* out = (float*)d_out;

    cudaFuncSetAttribute(gemm1_tc, cudaFuncAttributeMaxDynamicSharedMemorySize, 37888);
    cudaFuncSetAttribute(gemm2_tc, cudaFuncAttributeMaxDynamicSharedMemorySize, 61440);
    cudaFuncSetAttribute(pose_kernel, cudaFuncAttributeMaxDynamicSharedMemorySize, 70656);

    cvt_kernel<<<6657, 256>>>(W, lat);
    gemm1_tc<<<dim3(96, 8), 256, 37888>>>(base, W);
    pose_kernel<<<BP, 256, 70656>>>(tgt, stdq, meanq, offs, idisp, tdisp, mu, lv);
    gemm2_tc<<<dim3(2, 4, 32), 256, 61440>>>();
    cons_kernel<<<512, 256>>>(lat, out);
}

// round 16
// speedup vs baseline: 1.0320x; 1.0156x over previous
#include <cuda_runtime.h>
#include <cuda_bf16.h>
#include <cstdint>

#define BP 512
#define CC 96
#define TT 128
#define JJ 24
#define ZZ 256
#define CT 12288
#define N2 1024

__device__ __nv_bfloat16  g_qsb[(size_t)N2 * CT];    // decoded motion bf16
__device__ __nv_bfloat16  g_dqsb[(size_t)BP * CT];   // d f / d qs (bf16)
__device__ float          g_grad[(size_t)BP * ZZ];   // grad wrt latent[:,0]
__device__ double         g_acc[6];                  // root joints fk kld disp cons
__device__ unsigned int   g_cnt;                     // cons arrival counter
__device__ __nv_bfloat16  g_W2[(size_t)ZZ * CT];     // W bf16, [z][ct] (filled by gemm1)
__device__ uint32_t       g_W1[(size_t)(ZZ / 2) * CT]; // W bf16 k-pair packed [k2][n]
__device__ __nv_bfloat16  g_latb[(size_t)N2 * ZZ];   // latent bf16

// ---------------------------------------------------------------------------
// cvt: W1 (k-pair packed) + latent -> bf16, plus zero-init. (~13 MB traffic)
__global__ void cvt_kernel(const float* __restrict__ W, const float* __restrict__ lat)
{
    const int NW1 = (ZZ / 2) * CT;       // 1572864
    const int NL  = (N2 * ZZ) / 2;       // 131072
    int i = blockIdx.x * blockDim.x + threadIdx.x;
    if (i < BP * ZZ) g_grad[i] = 0.f;
    if (i < 6)       g_acc[i] = 0.0;
    if (i == 6)      g_cnt = 0u;
    if (i < NW1) {
        int k2 = i / CT, n = i - k2 * CT;
        float lo = W[(size_t)(2 * k2) * CT + n];
        float hi = W[(size_t)(2 * k2 + 1) * CT + n];
        __nv_bfloat162 h = __floats2bfloat162_rn(lo, hi);
        g_W1[i] = *reinterpret_cast<uint32_t*>(&h);
    } else if (i < NW1 + NL) {
        int j = i - NW1;
        float2 v = reinterpret_cast<const float2*>(lat)[j];
        reinterpret_cast<__nv_bfloat162*>(g_latb)[j] = __floats2bfloat162_rn(v.x, v.y);
    }
}

// ---------------------------------------------------------------------------
__device__ __forceinline__ float blockReduce(float v, float* sm) {
#pragma unroll
    for (int o = 16; o > 0; o >>= 1) v += __shfl_down_sync(0xffffffffu, v, o);
    int lane = threadIdx.x & 31, w = threadIdx.x >> 5;
    if (lane == 0) sm[w] = v;
    __syncthreads();
    v = 0.f;
    if (threadIdx.x < 32) {
        int nw = (blockDim.x + 31) >> 5;
        v = (threadIdx.x < nw) ? sm[threadIdx.x] : 0.f;
#pragma unroll
        for (int o = 16; o > 0; o >>= 1) v += __shfl_down_sync(0xffffffffu, v, o);
    }
    return v;
}

// ---------------------------------------------------------------------------
__device__ __forceinline__ void cp16(uint32_t dst, const void* src) {
    asm volatile("cp.async.ca.shared.global [%0], [%1], 16;\n" :: "r"(dst), "l"(src));
}
#define CP_COMMIT() asm volatile("cp.async.commit_group;\n")
#define CP_WAIT1()  asm volatile("cp.async.wait_group 1;\n")

__device__ __forceinline__ void mma_bf16(float& c0, float& c1, float& c2, float& c3,
                                         uint32_t a0, uint32_t a1, uint32_t a2, uint32_t a3,
                                         uint32_t b0, uint32_t b1)
{
    asm volatile("mma.sync.aligned.m16n8k16.row.col.f32.bf16.bf16.f32 "
                 "{%0,%1,%2,%3}, {%4,%5,%6,%7}, {%8,%9}, {%0,%1,%2,%3};"
                 : "+f"(c0), "+f"(c1), "+f"(c2), "+f"(c3)
                 : "r"(a0), "r"(a1), "r"(a2), "r"(a3), "r"(b0), "r"(b1));
}

__device__ __forceinline__ void ldsm_x4(uint32_t* r, uint32_t addr) {
    asm volatile("ldmatrix.sync.aligned.m8n8.x4.shared.b16 {%0,%1,%2,%3}, [%4];"
                 : "=r"(r[0]), "=r"(r[1]), "=r"(r[2]), "=r"(r[3]) : "r"(addr));
}
__device__ __forceinline__ void ldsm_x2(uint32_t* r, uint32_t addr) {
    asm volatile("ldmatrix.sync.aligned.m8n8.x2.shared.b16 {%0,%1}, [%2];"
                 : "=r"(r[0]), "=r"(r[1]) : "r"(addr));
}

// ---------------------------------------------------------------------------
// GEMM1 (bf16 m16n8k16, cp.async 2-stage, A-frags via ldmatrix):
// g_qsb = latb(1024x256)@W1 + base. Also converts W -> g_W2 (for gemm2).
__global__ __launch_bounds__(256, 2) void gemm1_tc(const float* __restrict__ base,
                                                   const float* __restrict__ W)
{
    extern __shared__ uint32_t smem[];
    uint32_t* AsU = smem;                 // 2 * 2560
    uint32_t* BsU = smem + 5120;          // 2 * 2176
    const uint32_t sA = (uint32_t)__cvta_generic_to_shared(AsU);
    const uint32_t sB = (uint32_t)__cvta_generic_to_shared(BsU);

    const int tid  = threadIdx.x;
    const int lane = tid & 31;
    const int wid  = tid >> 5;
    const int wm   = wid & 1;
    const int wn   = wid >> 1;
    const int g    = lane >> 2;
    const int tg   = lane & 3;
    const int bm   = blockIdx.y << 7;
    const int bn   = blockIdx.x << 7;

    const int lr       = lane & 7;
    const int rowShift = ((lane >> 3) & 1) << 3;
    const int kShift   = (lane >> 4) << 2;

    float acc[4][4][4];
#pragma unroll
    for (int i = 0; i < 4; i++)
#pragma unroll
        for (int j = 0; j < 4; j++)
#pragma unroll
            for (int c = 0; c < 4; c++) acc[i][j][c] = 0.f;

    auto loadTiles = [&](int kb, int s) {
#pragma unroll
        for (int it = 0; it < 2; it++) {
            int f = tid + it * 256;
            int m = f >> 2, cq = f & 3;
            cp16(sA + ((s * 2560 + m * 20 + cq * 4) << 2),
                 &g_latb[(size_t)(bm + m) * ZZ + kb + cq * 8]);
        }
        int kb2 = kb >> 1;
#pragma unroll
        for (int it = 0; it < 2; it++) {
            int f = tid + it * 256;
            int k2 = f >> 5, nq = f & 31;
            cp16(sB + ((s * 2176 + k2 * 136 + nq * 4) << 2),
                 &g_W1[(size_t)(kb2 + k2) * CT + bn + nq * 4]);
        }
    };

    loadTiles(0, 0);
    CP_COMMIT();

    // absorbed: W -> g_W2 (bf16) while pipeline warms up
    {
        const int NW = (ZZ * CT) / 2;
        int flat = (blockIdx.y * gridDim.x + blockIdx.x) * 256 + tid;
        const int stride = gridDim.x * gridDim.y * 256;
        for (int p = flat; p < NW; p += stride) {
            float2 v = reinterpret_cast<const float2*>(W)[p];
            reinterpret_cast<__nv_bfloat162*>(g_W2)[p] = __floats2bfloat162_rn(v.x, v.y);
        }
    }

    const int NK = ZZ / 32;  // 8
    for (int kt = 0; kt < NK; kt++) {
        if (kt + 1 < NK) loadTiles((kt + 1) * 32, (kt + 1) & 1);
        CP_COMMIT();
        CP_WAIT1();
        __syncthreads();

        const uint32_t aStage = (kt & 1) * 2560;
        const uint32_t* bs = BsU + (kt & 1) * 2176;
#pragma unroll
        for (int ks = 0; ks < 2; ks++) {
            const int kc2 = ks * 8;
            uint32_t afr[4][4];
#pragma unroll
            for (int i = 0; i < 4; i++) {
                int r0b = wm * 64 + i * 16;
                uint32_t aw = aStage + (uint32_t)(r0b + lr + rowShift) * 20 + kc2 + kShift;
                ldsm_x4(afr[i], sA + (aw << 2));
            }
            uint32_t bfr[4][2];
#pragma unroll
            for (int j = 0; j < 4; j++) {
                int c0 = wn * 32 + j * 8 + g;
                bfr[j][0] = bs[(kc2 + tg) * 136 + c0];
                bfr[j][1] = bs[(kc2 + tg + 4) * 136 + c0];
            }
#pragma unroll
            for (int i = 0; i < 4; i++)
#pragma unroll
                for (int j = 0; j < 4; j++)
                    mma_bf16(acc[i][j][0], acc[i][j][1], acc[i][j][2], acc[i][j][3],
                             afr[i][0], afr[i][1], afr[i][2], afr[i][3],
                             bfr[j][0], bfr[j][1]);
        }
        __syncthreads();
    }

#pragma unroll
    for (int i = 0; i < 4; i++) {
#pragma unroll
        for (int j = 0; j < 4; j++) {
            int row0 = bm + wm * 64 + i * 16 + g;
            int col  = bn + wn * 32 + j * 8 + 2 * tg;
            {
                size_t o = (size_t)row0 * CT + col;
                float2 bv = *reinterpret_cast<const float2*>(&base[o]);
                *reinterpret_cast<__nv_bfloat162*>(&g_qsb[o]) =
                    __floats2bfloat162_rn(acc[i][j][0] + bv.x, acc[i][j][1] + bv.y);
            }
            {
                size_t o = (size_t)(row0 + 8) * CT + col;
                float2 bv = *reinterpret_cast<const float2*>(&base[o]);
                *reinterpret_cast<__nv_bfloat162*>(&g_qsb[o]) =
                    __floats2bfloat162_rn(acc[i][j][2] + bv.x, acc[i][j][3] + bv.y);
            }
        }
    }
}

// ---------------------------------------------------------------------------
// GEMM2 (bf16, cp.async 3-stage, split-K=32, ldmatrix fragments).
// Absorbs disp/KLD reductions AFTER the mainloop (overlaps epilogue/tail).
__global__ __launch_bounds__(256, 2) void gemm2_tc(const float* __restrict__ id,
                                                   const float* __restrict__ td,
                                                   const float* __restrict__ mu,
                                                   const float* __restrict__ lv)
{
    extern __shared__ uint32_t smem[];
    __shared__ float s_red[32];
    uint32_t* AsU = smem;                 // 3 * 2560
    uint32_t* WsU = smem + 7680;          // 3 * 2560
    const uint32_t sA = (uint32_t)__cvta_generic_to_shared(AsU);
    const uint32_t sW = (uint32_t)__cvta_generic_to_shared(WsU);

    const int tid  = threadIdx.x;
    const int lane = tid & 31;
    const int wid  = tid >> 5;
    const int wm   = wid & 1;
    const int wn   = wid >> 1;
    const int bm   = blockIdx.y << 7;
    const int bn   = blockIdx.x << 7;
    const int k0s  = blockIdx.z * (CT / 32);

    const int lr       = lane & 7;
    const int rowShift = ((lane >> 3) & 1) << 3;
    const int kShift   = (lane >> 4) << 2;
    const int selB     = ((lane >> 3) & 1) << 2;

    float acc[4][4][4];
#pragma unroll
    for (int i = 0; i < 4; i++)
#pragma unroll
        for (int j = 0; j < 4; j++)
#pragma unroll
            for (int c = 0; c < 4; c++) acc[i][j][c] = 0.f;

    auto loadTiles = [&](int kb, int s) {
#pragma unroll
        for (int it = 0; it < 2; it++) {
            int f = tid + it * 256;
            int m = f >> 2, cq = f & 3;
            cp16(sA + ((s * 2560 + m * 20 + cq * 4) << 2),
                 &g_dqsb[(size_t)(bm + m) * CT + kb + cq * 8]);
        }
#pragma unroll
        for (int it = 0; it < 2; it++) {
            int f = tid + it * 256;
            int z = f >> 2, cq = f & 3;
            cp16(sW + ((s * 2560 + z * 20 + cq * 4) << 2),
                 &g_W2[(size_t)(bn + z) * CT + kb + cq * 8]);
        }
    };

    loadTiles(k0s, 0);      CP_COMMIT();
    loadTiles(k0s + 32, 1); CP_COMMIT();

    const int NK = (CT / 32) / 32;  // 12
    int stage = 0;
    int lstage = 2;
    for (int kt = 0; kt < NK; kt++) {
        CP_WAIT1();
        __syncthreads();
        if (kt + 2 < NK) {
            loadTiles(k0s + (kt + 2) * 32, lstage);
            if (++lstage == 3) lstage = 0;
        }
        CP_COMMIT();

        const uint32_t base = stage * 2560;
        if (++stage == 3) stage = 0;
#pragma unroll
        for (int ks = 0; ks < 2; ks++) {
            const int kc2 = ks * 8;
            uint32_t afr[4][4];
#pragma unroll
            for (int i = 0; i < 4; i++) {
                int r0b = wm * 64 + i * 16;
                uint32_t aw = base + (uint32_t)(r0b + lr + rowShift) * 20 + kc2 + kShift;
                ldsm_x4(afr[i], sA + (aw << 2));
            }
            uint32_t bfr[4][2];
#pragma unroll
            for (int j = 0; j < 4; j++) {
                int c0b = wn * 32 + j * 8;
                uint32_t bw = base + (uint32_t)(c0b + lr) * 20 + kc2 + selB;
                ldsm_x2(bfr[j], sW + (bw << 2));
            }
#pragma unroll
            for (int i = 0; i < 4; i++)
#pragma unroll
                for (int j = 0; j < 4; j++)
                    mma_bf16(acc[i][j][0], acc[i][j][1], acc[i][j][2], acc[i][j][3],
                             afr[i][0], afr[i][1], afr[i][2], afr[i][3],
                             bfr[j][0], bfr[j][1]);
        }
    }

    // epilogue atomics
    const int g  = lane >> 2;
    const int tg = lane & 3;
#pragma unroll
    for (int i = 0; i < 4; i++)
#pragma unroll
        for (int j = 0; j < 4; j++) {
            int row0 = bm + wm * 64 + i * 16 + g;
            int col  = bn + wn * 32 + j * 8 + 2 * tg;
            atomicAdd(&g_grad[(size_t)row0 * ZZ + col],           acc[i][j][0]);
            atomicAdd(&g_grad[(size_t)row0 * ZZ + col + 1],       acc[i][j][1]);
            atomicAdd(&g_grad[(size_t)(row0 + 8) * ZZ + col],     acc[i][j][2]);
            atomicAdd(&g_grad[(size_t)(row0 + 8) * ZZ + col + 1], acc[i][j][3]);
        }

    // absorbed disp/KLD (after mainloop: overlaps epilogue + tail imbalance)
    {
        int flat = ((blockIdx.z * gridDim.y + blockIdx.y) * gridDim.x + blockIdx.x) * 256 + tid;
        const int stride = gridDim.x * gridDim.y * gridDim.z * 256;  // 65536
        float sd = 0.f, sk = 0.f;
        for (int k = flat; k < BP * 2 * 3 * TT; k += stride) {
            float df = id[k] - td[k]; sd += df * df;
        }
        for (int k = flat; k < N2 * ZZ; k += stride) {
            float m = mu[k], l = lv[k];
            sk += 1.0f + l - m * m - expf(l);
        }
        float r = blockReduce(sd, s_red);
        if (tid == 0) atomicAdd(&g_acc[4], (double)r);
        __syncthreads();
        r = blockReduce(sk, s_red);
        if (tid == 0) atomicAdd(&g_acc[3], (double)r);
    }
}

// ---------------------------------------------------------------------------
__device__ __forceinline__ void qrot(const float* __restrict__ q,
                                     const float* __restrict__ v,
                                     float* __restrict__ r)
{
    float w = q[0], x = q[1], y = q[2], z = q[3];
    float inv = 1.0f / (w * w + x * x + y * y + z * z);
    float a = w * w - (x * x + y * y + z * z);
    float d = 2.0f * (x * v[0] + y * v[1] + z * v[2]);
    float cx = y * v[2] - z * v[1];
    float cy = z * v[0] - x * v[2];
    float cz = x * v[1] - y * v[0];
    float tw = 2.0f * w;
    r[0] = (a * v[0] + d * x + tw * cx) * inv;
    r[1] = (a * v[1] + d * y + tw * cy) * inv;
    r[2] = (a * v[2] + d * z + tw * cz) * inv;
}

__device__ __forceinline__ void qrot_bwd(const float* __restrict__ q,
                                         const float* __restrict__ v,
                                         const float* __restrict__ g,
                                         float& dw, float& dx, float& dy, float& dz)
{
    float w = q[0], x = q[1], y = q[2], z = q[3];
    float inv = 1.0f / (w * w + x * x + y * y + z * z);
    float a = w * w - (x * x + y * y + z * z);
    float dd = 2.0f * (x * v[0] + y * v[1] + z * v[2]);
    float cx = y * v[2] - z * v[1];
    float cy = z * v[0] - x * v[2];
    float cz = x * v[1] - y * v[0];
    float tw = 2.0f * w;
    float r0 = (a * v[0] + dd * x + tw * cx) * inv;
    float r1 = (a * v[1] + dd * y + tw * cy) * inv;
    float r2 = (a * v[2] + dd * z + tw * cz) * inv;
    float c1 = v[0] * g[0] + v[1] * g[1] + v[2] * g[2];
    float c2 = x * g[0] + y * g[1] + z * g[2];
    float c3 = 0.5f * dd;
    float gr = g[0] * r0 + g[1] * r1 + g[2] * r2;
    float cg = cx * g[0] + cy * g[1] + cz * g[2];
    float s = 2.0f * inv;
    float vgx = v[1] * g[2] - v[2] * g[1];
    float vgy = v[2] * g[0] - v[0] * g[2];
    float vgz = v[0] * g[1] - v[1] * g[0];
    dw += s * (w * c1 + cg - w * gr);
    dx += s * (-c1 * x + c2 * v[0] + c3 * g[0] + w * vgx - gr * x);
    dy += s * (-c1 * y + c2 * v[1] + c3 * g[1] + w * vgy - gr * y);
    dz += s * (-c1 * z + c2 * v[2] + c3 * g[2] + w * vgz - gr * z);
}

// ---------------------------------------------------------------------------
// Pose kernel: k-split, pd in SMEM (69 rows x 256), qs read as bf16. (pure)
#define SPD(r) s_pd[((r) - 3) * 256]
__global__ __launch_bounds__(256, 3) void pose_kernel(const float* __restrict__ tgt,
                                                      const float* __restrict__ stdq,
                                                      const float* __restrict__ meanq,
                                                      const float* __restrict__ offs)
{
    extern __shared__ float s_pd[];          // 69*256 floats
    __shared__ float s_std[CC], s_mean[CC], s_off[JJ * 3];
    __shared__ float s_red[32];
    const int b  = blockIdx.x;
    const int t  = threadIdx.x;
    const int tk = t >> 7;
    const int tt = t & 127;
    if (t < CC) { s_std[t] = stdq[t]; s_mean[t] = meanq[t]; }
    if (t >= 128 && t < 128 + JJ * 3) s_off[t - 128] = offs[b * JJ * 3 + (t - 128)];
    __syncthreads();

    float accR = 0.f, accJ = 0.f, accF = 0.f;

    const __nv_bfloat16* dbase = g_qsb + (size_t)(b * 2 + tk) * CT + tt;
    const float* tbase = tgt + (size_t)(b * 2 + tk) * (2 * CT) + tt;

    {
#pragma unroll
        for (int i = 0; i < 4; i++) {
            float df = __bfloat162float(dbase[(size_t)i * TT]) - tbase[(size_t)i * TT];
            accR += df * df;
        }
        const int leaves[5] = { 10, 11, 15, 22, 23 };
#pragma unroll
        for (int e = 0; e < 5; e++) {
            int j = leaves[e];
#pragma unroll
            for (int i = 0; i < 4; i++) {
                float df = __bfloat162float(dbase[(size_t)(4 * j + i) * TT])
                         - tbase[(size_t)(8 * j + i) * TT];
                accJ += df * df;
            }
        }
    }

    {
        float qD[4], qT[4];
        float pDx, pDy, pDz, pTx, pTy, pTz;

        auto loadPair = [&](int j) {
#pragma unroll
            for (int i = 0; i < 4; i++) {
                int c = 4 * j + i;
                float d  = __bfloat162float(dbase[(size_t)c * TT]);
                float tr = tbase[(size_t)(8 * j + i) * TT];
                float df = d - tr;
                accJ += df * df;
                qD[i] = d * s_std[c] + s_mean[c];
                qT[i] = tr * s_std[c] + s_mean[c];
            }
        };
        auto step = [&](int j) {
            const float* v = s_off + 3 * j;
            float r[3];
            qrot(qD, v, r); pDx += r[0]; pDy += r[1]; pDz += r[2];
            qrot(qT, v, r); pTx += r[0]; pTy += r[1]; pTz += r[2];
            float dx = pDx - pTx, dy = pDy - pTy, dz = pDz - pTz;
            accF += dx * dx + dy * dy + dz * dz;
            (&SPD(3 * j + 0))[t] = pDx;
            (&SPD(3 * j + 1))[t] = pDy;
            (&SPD(3 * j + 2))[t] = pDz;
        };
        auto reset = [&]() {
            pDx = pDy = pDz = pTx = pTy = pTz = 0.f;
            qD[0] = 1.f; qD[1] = qD[2] = qD[3] = 0.f;
            qT[0] = 1.f; qT[1] = qT[2] = qT[3] = 0.f;
        };

        reset();
        step(1); loadPair(1); step(4); loadPair(4); step(7); loadPair(7); step(10);
        reset();
        step(2); loadPair(2); step(5); loadPair(5); step(8); loadPair(8); step(11);
        reset();
        step(3); loadPair(3); step(6); loadPair(6); step(9); loadPair(9);
        float sp[6] = { pDx, pDy, pDz, pTx, pTy, pTz };
        float sqD[4] = { qD[0], qD[1], qD[2], qD[3] };
        float sqT[4] = { qT[0], qT[1], qT[2], qT[3] };
        step(12); loadPair(12); step(15);
        pDx = sp[0]; pDy = sp[1]; pDz = sp[2]; pTx = sp[3]; pTy = sp[4]; pTz = sp[5];
        qD[0] = sqD[0]; qD[1] = sqD[1]; qD[2] = sqD[2]; qD[3] = sqD[3];
        qT[0] = sqT[0]; qT[1] = sqT[1]; qT[2] = sqT[2]; qT[3] = sqT[3];
        step(13); loadPair(13); step(16); loadPair(16); step(18); loadPair(18);
        step(20); loadPair(20); step(22);
        pDx = sp[0]; pDy = sp[1]; pDz = sp[2]; pTx = sp[3]; pTy = sp[4]; pTz = sp[5];
        qD[0] = sqD[0]; qD[1] = sqD[1]; qD[2] = sqD[2]; qD[3] = sqD[3];
        qT[0] = sqT[0]; qT[1] = sqT[1]; qT[2] = sqT[2]; qT[3] = sqT[3];
        step(14); loadPair(14); step(17); loadPair(17); step(19); loadPair(19);
        step(21); loadPair(21); step(23);
    }
    __syncthreads();

    if (tk == 0) {
#pragma unroll
        for (int r = 3; r < 72; r++) {
            float* row = &SPD(r);
            float v = row[tt];
            row[tt] = 2.f * (v - row[tt + 128]);
        }
        const int ch[20] = { 23,22,21,20,19,18,17,16,15,14,13,12,11,10,9,8,7,6,5,4 };
        const int pa[20] = { 21,20,19,18,17,16,14,13,12, 9, 9, 9, 8, 7, 6, 5, 4, 3, 2, 1 };
#pragma unroll
        for (int e = 0; e < 20; e++) {
            int cj = ch[e], pj = pa[e];
#pragma unroll
            for (int i = 0; i < 3; i++)
                (&SPD(3 * pj + i))[tt] += (&SPD(3 * cj + i))[tt];
        }
    }
    __syncthreads();

    __nv_bfloat16* outp = g_dqsb + (size_t)b * CT + tt;
    const __nv_bfloat16* dbase0 = g_qsb + (size_t)(b * 2) * CT + tt;
    auto doParent = [&](int p, int c0, int c1, int c2) {
        float q[4];
#pragma unroll
        for (int i = 0; i < 4; i++) {
            int c = 4 * p + i;
            q[i] = __bfloat162float(dbase0[(size_t)c * TT]) * s_std[c] + s_mean[c];
        }
        float dw = 0.f, dx = 0.f, dy = 0.f, dz = 0.f;
        float gv[3];
        gv[0] = (&SPD(3 * c0 + 0))[tt];
        gv[1] = (&SPD(3 * c0 + 1))[tt];
        gv[2] = (&SPD(3 * c0 + 2))[tt];
        qrot_bwd(q, s_off + 3 * c0, gv, dw, dx, dy, dz);
        if (c1 >= 0) {
            gv[0] = (&SPD(3 * c1 + 0))[tt];
            gv[1] = (&SPD(3 * c1 + 1))[tt];
            gv[2] = (&SPD(3 * c1 + 2))[tt];
            qrot_bwd(q, s_off + 3 * c1, gv, dw, dx, dy, dz);
        }
        if (c2 >= 0) {
            gv[0] = (&SPD(3 * c2 + 0))[tt];
            gv[1] = (&SPD(3 * c2 + 1))[tt];
            gv[2] = (&SPD(3 * c2 + 2))[tt];
            qrot_bwd(q, s_off + 3 * c2, gv, dw, dx, dy, dz);
        }
        outp[(size_t)(4 * p + 0) * TT] = __float2bfloat16_rn(dw * s_std[4 * p + 0]);
        outp[(size_t)(4 * p + 1) * TT] = __float2bfloat16_rn(dx * s_std[4 * p + 1]);
        outp[(size_t)(4 * p + 2) * TT] = __float2bfloat16_rn(dy * s_std[4 * p + 2]);
        outp[(size_t)(4 * p + 3) * TT] = __float2bfloat16_rn(dz * s_std[4 * p + 3]);
    };
    const __nv_bfloat16 bz = __float2bfloat16_rn(0.f);
    if (tk == 0) {
        const int zj[3] = { 0, 10, 11 };
#pragma unroll
        for (int e = 0; e < 3; e++)
#pragma unroll
            for (int i = 0; i < 4; i++)
                outp[(size_t)(4 * zj[e] + i) * TT] = bz;
        doParent(1, 4, -1, -1);  doParent(2, 5, -1, -1);  doParent(3, 6, -1, -1);
        doParent(4, 7, -1, -1);  doParent(5, 8, -1, -1);  doParent(6, 9, -1, -1);
        doParent(7, 10, -1, -1); doParent(8, 11, -1, -1);
        doParent(9, 12, 13, 14);
    } else {
        const int zj[3] = { 15, 22, 23 };
#pragma unroll
        for (int e = 0; e < 3; e++)
#pragma unroll
            for (int i = 0; i < 4; i++)
                outp[(size_t)(4 * zj[e] + i) * TT] = bz;
        doParent(12, 15, -1, -1); doParent(13, 16, -1, -1); doParent(14, 17, -1, -1);
        doParent(16, 18, -1, -1); doParent(17, 19, -1, -1); doParent(18, 20, -1, -1);
        doParent(19, 21, -1, -1); doParent(20, 22, -1, -1); doParent(21, 23, -1, -1);
    }

    float r = blockReduce(accR, s_red);
    if (threadIdx.x == 0) atomicAdd(&g_acc[0], (double)r);
    __syncthreads();
    r = blockReduce(accJ, s_red);
    if (threadIdx.x == 0) atomicAdd(&g_acc[1], (double)r);
    __syncthreads();
    r = blockReduce(accF, s_red);
    if (threadIdx.x == 0) atomicAdd(&g_acc[2], (double)r);
}

// ---------------------------------------------------------------------------
// cons loss only; last arriving block finalizes the output.
__global__ void cons_kernel(const float* __restrict__ lat, float* __restrict__ out)
{
    __shared__ float s_red[32];
    int i = blockIdx.x * blockDim.x + threadIdx.x;
    int b = i >> 8, z = i & 255;
    float d = lat[(size_t)(2 * b) * ZZ + z] - g_grad[i] - lat[(size_t)(2 * b + 1) * ZZ + z];
    float r = blockReduce(d * d, s_red);
    if (threadIdx.x == 0) atomicAdd(&g_acc[5], (double)r);

    if (threadIdx.x == 0) {
        __threadfence();
        unsigned int c = atomicAdd(&g_cnt, 1u);
        if (c == gridDim.x - 1) {
            out[0] = (float)(-0.5 * g_acc[3] / 1024.0) * 0.001f;
            out[1] = (float)(g_acc[0] / 524288.0);
            out[2] = (float)(g_acc[4] / 393216.0);
            out[3] = (float)(g_acc[5] / 131072.0) * 0.1f;
            out[4] = (float)(g_acc[2] / 9437184.0) * 0.1f;
            out[5] = (float)(g_acc[1] / 12058624.0);
        }
    }
}

// ---------------------------------------------------------------------------
extern "C" void kernel_launch(void* const* d_in, const int* in_sizes, int n_in,
                              void* d_out, int out_size)
{
    const float* base  = (const float*)d_in[0];
    const float* tgt   = (const float*)d_in[1];
    const float* idisp = (const float*)d_in[2];
    const float* tdisp = (const float*)d_in[3];
    const float* mu    = (const float*)d_in[4];
    const float* lv    = (const float*)d_in[5];
    const float* lat   = (const float*)d_in[6];
    const float* W     = (const float*)d_in[7];
    const float* meanq = (const float*)d_in[8];
    const float* stdq  = (const float*)d_in[9];
    const float* offs  = (const float*)d_in[10];
    float* out = (float*)d_out;

    cudaFuncSetAttribute(gemm1_tc, cudaFuncAttributeMaxDynamicSharedMemorySize, 37888);
    cudaFuncSetAttribute(gemm2_tc, cudaFuncAttributeMaxDynamicSharedMemorySize, 61440);
    cudaFuncSetAttribute(pose_kernel, cudaFuncAttributeMaxDynamicSharedMemorySize, 70656);

    cvt_kernel<<<6657, 256>>>(W, lat);
    gemm1_tc<<<dim3(96, 8), 256, 37888>>>(base, W);
    pose_kernel<<<BP, 256, 70656>>>(tgt, stdq, meanq, offs);
    gemm2_tc<<<dim3(2, 4, 32), 256, 61440>>>(idisp, tdisp, mu, lv);
    cons_kernel<<<512, 256>>>(lat, out);
}

// round 17
// speedup vs baseline: 1.0616x; 1.0287x over previous
#include <cuda_runtime.h>
#include <cuda_bf16.h>
#include <cstdint>

#define BP 512
#define CC 96
#define TT 128
#define JJ 24
#define ZZ 256
#define CT 12288
#define N2 1024

__device__ __nv_bfloat16  g_qsb[(size_t)N2 * CT];    // decoded motion bf16
__device__ __nv_bfloat16  g_dqsb[(size_t)BP * CT];   // d f / d qs (bf16)
__device__ float          g_grad[(size_t)BP * ZZ];   // grad wrt latent[:,0]
__device__ double         g_acc[6];                  // root joints fk kld disp cons
__device__ unsigned int   g_cnt;                     // cons arrival counter
__device__ __nv_bfloat16  g_W2[(size_t)ZZ * CT];     // W bf16, [z][ct] (filled by gemm1)
__device__ uint32_t       g_W1[(size_t)(ZZ / 2) * CT]; // W bf16 k-pair packed [k2][n]
__device__ __nv_bfloat16  g_latb[(size_t)N2 * ZZ];   // latent bf16

// ---------------------------------------------------------------------------
// cvt: W1 (k-pair packed) + latent -> bf16, plus zero-init. (~13 MB traffic)
__global__ void cvt_kernel(const float* __restrict__ W, const float* __restrict__ lat)
{
    const int NW1 = (ZZ / 2) * CT;       // 1572864
    const int NL  = (N2 * ZZ) / 2;       // 131072
    int i = blockIdx.x * blockDim.x + threadIdx.x;
    if (i < BP * ZZ) g_grad[i] = 0.f;
    if (i < 6)       g_acc[i] = 0.0;
    if (i == 6)      g_cnt = 0u;
    if (i < NW1) {
        int k2 = i / CT, n = i - k2 * CT;
        float lo = W[(size_t)(2 * k2) * CT + n];
        float hi = W[(size_t)(2 * k2 + 1) * CT + n];
        __nv_bfloat162 h = __floats2bfloat162_rn(lo, hi);
        g_W1[i] = *reinterpret_cast<uint32_t*>(&h);
    } else if (i < NW1 + NL) {
        int j = i - NW1;
        float2 v = reinterpret_cast<const float2*>(lat)[j];
        reinterpret_cast<__nv_bfloat162*>(g_latb)[j] = __floats2bfloat162_rn(v.x, v.y);
    }
}

// ---------------------------------------------------------------------------
__device__ __forceinline__ float blockReduce(float v, float* sm) {
#pragma unroll
    for (int o = 16; o > 0; o >>= 1) v += __shfl_down_sync(0xffffffffu, v, o);
    int lane = threadIdx.x & 31, w = threadIdx.x >> 5;
    if (lane == 0) sm[w] = v;
    __syncthreads();
    v = 0.f;
    if (threadIdx.x < 32) {
        int nw = (blockDim.x + 31) >> 5;
        v = (threadIdx.x < nw) ? sm[threadIdx.x] : 0.f;
#pragma unroll
        for (int o = 16; o > 0; o >>= 1) v += __shfl_down_sync(0xffffffffu, v, o);
    }
    return v;
}

// ---------------------------------------------------------------------------
__device__ __forceinline__ void cp16(uint32_t dst, const void* src) {
    asm volatile("cp.async.ca.shared.global [%0], [%1], 16;\n" :: "r"(dst), "l"(src));
}
#define CP_COMMIT() asm volatile("cp.async.commit_group;\n")
#define CP_WAIT1()  asm volatile("cp.async.wait_group 1;\n")

__device__ __forceinline__ void mma_bf16(float& c0, float& c1, float& c2, float& c3,
                                         uint32_t a0, uint32_t a1, uint32_t a2, uint32_t a3,
                                         uint32_t b0, uint32_t b1)
{
    asm volatile("mma.sync.aligned.m16n8k16.row.col.f32.bf16.bf16.f32 "
                 "{%0,%1,%2,%3}, {%4,%5,%6,%7}, {%8,%9}, {%0,%1,%2,%3};"
                 : "+f"(c0), "+f"(c1), "+f"(c2), "+f"(c3)
                 : "r"(a0), "r"(a1), "r"(a2), "r"(a3), "r"(b0), "r"(b1));
}

__device__ __forceinline__ void ldsm_x4(uint32_t* r, uint32_t addr) {
    asm volatile("ldmatrix.sync.aligned.m8n8.x4.shared.b16 {%0,%1,%2,%3}, [%4];"
                 : "=r"(r[0]), "=r"(r[1]), "=r"(r[2]), "=r"(r[3]) : "r"(addr));
}
__device__ __forceinline__ void ldsm_x2(uint32_t* r, uint32_t addr) {
    asm volatile("ldmatrix.sync.aligned.m8n8.x2.shared.b16 {%0,%1}, [%2];"
                 : "=r"(r[0]), "=r"(r[1]) : "r"(addr));
}

// ---------------------------------------------------------------------------
// GEMM1 (bf16 m16n8k16, cp.async 2-stage, A-frags via ldmatrix):
// g_qsb = latb(1024x256)@W1 + base. Also converts W -> g_W2 (for gemm2).
__global__ __launch_bounds__(256, 2) void gemm1_tc(const float* __restrict__ base,
                                                   const float* __restrict__ W)
{
    extern __shared__ uint32_t smem[];
    uint32_t* AsU = smem;                 // 2 * 2560
    uint32_t* BsU = smem + 5120;          // 2 * 2176
    const uint32_t sA = (uint32_t)__cvta_generic_to_shared(AsU);
    const uint32_t sB = (uint32_t)__cvta_generic_to_shared(BsU);

    const int tid  = threadIdx.x;
    const int lane = tid & 31;
    const int wid  = tid >> 5;
    const int wm   = wid & 1;
    const int wn   = wid >> 1;
    const int g    = lane >> 2;
    const int tg   = lane & 3;
    const int bm   = blockIdx.y << 7;
    const int bn   = blockIdx.x << 7;

    const int lr       = lane & 7;
    const int rowShift = ((lane >> 3) & 1) << 3;
    const int kShift   = (lane >> 4) << 2;

    float acc[4][4][4];
#pragma unroll
    for (int i = 0; i < 4; i++)
#pragma unroll
        for (int j = 0; j < 4; j++)
#pragma unroll
            for (int c = 0; c < 4; c++) acc[i][j][c] = 0.f;

    auto loadTiles = [&](int kb, int s) {
#pragma unroll
        for (int it = 0; it < 2; it++) {
            int f = tid + it * 256;
            int m = f >> 2, cq = f & 3;
            cp16(sA + ((s * 2560 + m * 20 + cq * 4) << 2),
                 &g_latb[(size_t)(bm + m) * ZZ + kb + cq * 8]);
        }
        int kb2 = kb >> 1;
#pragma unroll
        for (int it = 0; it < 2; it++) {
            int f = tid + it * 256;
            int k2 = f >> 5, nq = f & 31;
            cp16(sB + ((s * 2176 + k2 * 136 + nq * 4) << 2),
                 &g_W1[(size_t)(kb2 + k2) * CT + bn + nq * 4]);
        }
    };

    loadTiles(0, 0);
    CP_COMMIT();

    // absorbed: W -> g_W2 (bf16) while pipeline warms up
    {
        const int NW = (ZZ * CT) / 2;
        int flat = (blockIdx.y * gridDim.x + blockIdx.x) * 256 + tid;
        const int stride = gridDim.x * gridDim.y * 256;
        for (int p = flat; p < NW; p += stride) {
            float2 v = reinterpret_cast<const float2*>(W)[p];
            reinterpret_cast<__nv_bfloat162*>(g_W2)[p] = __floats2bfloat162_rn(v.x, v.y);
        }
    }

    const int NK = ZZ / 32;  // 8
    for (int kt = 0; kt < NK; kt++) {
        if (kt + 1 < NK) loadTiles((kt + 1) * 32, (kt + 1) & 1);
        CP_COMMIT();
        CP_WAIT1();
        __syncthreads();

        const uint32_t aStage = (kt & 1) * 2560;
        const uint32_t* bs = BsU + (kt & 1) * 2176;
#pragma unroll
        for (int ks = 0; ks < 2; ks++) {
            const int kc2 = ks * 8;
            uint32_t afr[4][4];
#pragma unroll
            for (int i = 0; i < 4; i++) {
                int r0b = wm * 64 + i * 16;
                uint32_t aw = aStage + (uint32_t)(r0b + lr + rowShift) * 20 + kc2 + kShift;
                ldsm_x4(afr[i], sA + (aw << 2));
            }
            uint32_t bfr[4][2];
#pragma unroll
            for (int j = 0; j < 4; j++) {
                int c0 = wn * 32 + j * 8 + g;
                bfr[j][0] = bs[(kc2 + tg) * 136 + c0];
                bfr[j][1] = bs[(kc2 + tg + 4) * 136 + c0];
            }
#pragma unroll
            for (int i = 0; i < 4; i++)
#pragma unroll
                for (int j = 0; j < 4; j++)
                    mma_bf16(acc[i][j][0], acc[i][j][1], acc[i][j][2], acc[i][j][3],
                             afr[i][0], afr[i][1], afr[i][2], afr[i][3],
                             bfr[j][0], bfr[j][1]);
        }
        __syncthreads();
    }

#pragma unroll
    for (int i = 0; i < 4; i++) {
#pragma unroll
        for (int j = 0; j < 4; j++) {
            int row0 = bm + wm * 64 + i * 16 + g;
            int col  = bn + wn * 32 + j * 8 + 2 * tg;
            {
                size_t o = (size_t)row0 * CT + col;
                float2 bv = *reinterpret_cast<const float2*>(&base[o]);
                *reinterpret_cast<__nv_bfloat162*>(&g_qsb[o]) =
                    __floats2bfloat162_rn(acc[i][j][0] + bv.x, acc[i][j][1] + bv.y);
            }
            {
                size_t o = (size_t)(row0 + 8) * CT + col;
                float2 bv = *reinterpret_cast<const float2*>(&base[o]);
                *reinterpret_cast<__nv_bfloat162*>(&g_qsb[o]) =
                    __floats2bfloat162_rn(acc[i][j][2] + bv.x, acc[i][j][3] + bv.y);
            }
        }
    }
}

// ---------------------------------------------------------------------------
// GEMM2 (bf16, cp.async 3-stage, split-K=32, ldmatrix fragments).
// disp/KLD: float4 loads+math in prologue (round-13 best placement),
// blockReduce deferred to after the epilogue.
__global__ __launch_bounds__(256, 2) void gemm2_tc(const float* __restrict__ id,
                                                   const float* __restrict__ td,
                                                   const float* __restrict__ mu,
                                                   const float* __restrict__ lv)
{
    extern __shared__ uint32_t smem[];
    __shared__ float s_red[32];
    uint32_t* AsU = smem;                 // 3 * 2560
    uint32_t* WsU = smem + 7680;          // 3 * 2560
    const uint32_t sA = (uint32_t)__cvta_generic_to_shared(AsU);
    const uint32_t sW = (uint32_t)__cvta_generic_to_shared(WsU);

    const int tid  = threadIdx.x;
    const int lane = tid & 31;
    const int wid  = tid >> 5;
    const int wm   = wid & 1;
    const int wn   = wid >> 1;
    const int bm   = blockIdx.y << 7;
    const int bn   = blockIdx.x << 7;
    const int k0s  = blockIdx.z * (CT / 32);

    const int lr       = lane & 7;
    const int rowShift = ((lane >> 3) & 1) << 3;
    const int kShift   = (lane >> 4) << 2;
    const int selB     = ((lane >> 3) & 1) << 2;

    float acc[4][4][4];
#pragma unroll
    for (int i = 0; i < 4; i++)
#pragma unroll
        for (int j = 0; j < 4; j++)
#pragma unroll
            for (int c = 0; c < 4; c++) acc[i][j][c] = 0.f;

    auto loadTiles = [&](int kb, int s) {
#pragma unroll
        for (int it = 0; it < 2; it++) {
            int f = tid + it * 256;
            int m = f >> 2, cq = f & 3;
            cp16(sA + ((s * 2560 + m * 20 + cq * 4) << 2),
                 &g_dqsb[(size_t)(bm + m) * CT + kb + cq * 8]);
        }
#pragma unroll
        for (int it = 0; it < 2; it++) {
            int f = tid + it * 256;
            int z = f >> 2, cq = f & 3;
            cp16(sW + ((s * 2560 + z * 20 + cq * 4) << 2),
                 &g_W2[(size_t)(bn + z) * CT + kb + cq * 8]);
        }
    };

    loadTiles(k0s, 0);      CP_COMMIT();
    loadTiles(k0s + 32, 1); CP_COMMIT();

    // absorbed disp/KLD compute (float4, prologue; reduce deferred)
    float sd = 0.f, sk = 0.f;
    {
        int flat = ((blockIdx.z * gridDim.y + blockIdx.y) * gridDim.x + blockIdx.x) * 256 + tid;
        const int stride = gridDim.x * gridDim.y * gridDim.z * 256;  // 65536
        const float4* id4 = reinterpret_cast<const float4*>(id);
        const float4* td4 = reinterpret_cast<const float4*>(td);
        for (int k = flat; k < (BP * 2 * 3 * TT) / 4; k += stride) {
            float4 a = id4[k], b = td4[k];
            float dx = a.x - b.x, dy = a.y - b.y, dz = a.z - b.z, dw = a.w - b.w;
            sd += dx * dx + dy * dy + dz * dz + dw * dw;
        }
        const float4* mu4 = reinterpret_cast<const float4*>(mu);
        const float4* lv4 = reinterpret_cast<const float4*>(lv);
        for (int k = flat; k < (N2 * ZZ) / 4; k += stride) {
            float4 m = mu4[k], l = lv4[k];
            sk += 4.0f + (l.x + l.y + l.z + l.w)
                - (m.x * m.x + m.y * m.y + m.z * m.z + m.w * m.w)
                - (expf(l.x) + expf(l.y) + expf(l.z) + expf(l.w));
        }
    }

    const int NK = (CT / 32) / 32;  // 12
    int stage = 0;
    int lstage = 2;
    for (int kt = 0; kt < NK; kt++) {
        CP_WAIT1();
        __syncthreads();
        if (kt + 2 < NK) {
            loadTiles(k0s + (kt + 2) * 32, lstage);
            if (++lstage == 3) lstage = 0;
        }
        CP_COMMIT();

        const uint32_t base = stage * 2560;
        if (++stage == 3) stage = 0;
#pragma unroll
        for (int ks = 0; ks < 2; ks++) {
            const int kc2 = ks * 8;
            uint32_t afr[4][4];
#pragma unroll
            for (int i = 0; i < 4; i++) {
                int r0b = wm * 64 + i * 16;
                uint32_t aw = base + (uint32_t)(r0b + lr + rowShift) * 20 + kc2 + kShift;
                ldsm_x4(afr[i], sA + (aw << 2));
            }
            uint32_t bfr[4][2];
#pragma unroll
            for (int j = 0; j < 4; j++) {
                int c0b = wn * 32 + j * 8;
                uint32_t bw = base + (uint32_t)(c0b + lr) * 20 + kc2 + selB;
                ldsm_x2(bfr[j], sW + (bw << 2));
            }
#pragma unroll
            for (int i = 0; i < 4; i++)
#pragma unroll
                for (int j = 0; j < 4; j++)
                    mma_bf16(acc[i][j][0], acc[i][j][1], acc[i][j][2], acc[i][j][3],
                             afr[i][0], afr[i][1], afr[i][2], afr[i][3],
                             bfr[j][0], bfr[j][1]);
        }
    }

    // epilogue atomics
    const int g  = lane >> 2;
    const int tg = lane & 3;
#pragma unroll
    for (int i = 0; i < 4; i++)
#pragma unroll
        for (int j = 0; j < 4; j++) {
            int row0 = bm + wm * 64 + i * 16 + g;
            int col  = bn + wn * 32 + j * 8 + 2 * tg;
            atomicAdd(&g_grad[(size_t)row0 * ZZ + col],           acc[i][j][0]);
            atomicAdd(&g_grad[(size_t)row0 * ZZ + col + 1],       acc[i][j][1]);
            atomicAdd(&g_grad[(size_t)(row0 + 8) * ZZ + col],     acc[i][j][2]);
            atomicAdd(&g_grad[(size_t)(row0 + 8) * ZZ + col + 1], acc[i][j][3]);
        }

    // deferred reductions
    __syncthreads();
    float r = blockReduce(sd, s_red);
    if (tid == 0) atomicAdd(&g_acc[4], (double)r);
    __syncthreads();
    r = blockReduce(sk, s_red);
    if (tid == 0) atomicAdd(&g_acc[3], (double)r);
}

// ---------------------------------------------------------------------------
__device__ __forceinline__ void qrot(const float* __restrict__ q,
                                     const float* __restrict__ v,
                                     float* __restrict__ r)
{
    float w = q[0], x = q[1], y = q[2], z = q[3];
    float inv = 1.0f / (w * w + x * x + y * y + z * z);
    float a = w * w - (x * x + y * y + z * z);
    float d = 2.0f * (x * v[0] + y * v[1] + z * v[2]);
    float cx = y * v[2] - z * v[1];
    float cy = z * v[0] - x * v[2];
    float cz = x * v[1] - y * v[0];
    float tw = 2.0f * w;
    r[0] = (a * v[0] + d * x + tw * cx) * inv;
    r[1] = (a * v[1] + d * y + tw * cy) * inv;
    r[2] = (a * v[2] + d * z + tw * cz) * inv;
}

__device__ __forceinline__ void qrot_bwd(const float* __restrict__ q,
                                         const float* __restrict__ v,
                                         const float* __restrict__ g,
                                         float& dw, float& dx, float& dy, float& dz)
{
    float w = q[0], x = q[1], y = q[2], z = q[3];
    float inv = 1.0f / (w * w + x * x + y * y + z * z);
    float a = w * w - (x * x + y * y + z * z);
    float dd = 2.0f * (x * v[0] + y * v[1] + z * v[2]);
    float cx = y * v[2] - z * v[1];
    float cy = z * v[0] - x * v[2];
    float cz = x * v[1] - y * v[0];
    float tw = 2.0f * w;
    float r0 = (a * v[0] + dd * x + tw * cx) * inv;
    float r1 = (a * v[1] + dd * y + tw * cy) * inv;
    float r2 = (a * v[2] + dd * z + tw * cz) * inv;
    float c1 = v[0] * g[0] + v[1] * g[1] + v[2] * g[2];
    float c2 = x * g[0] + y * g[1] + z * g[2];
    float c3 = 0.5f * dd;
    float gr = g[0] * r0 + g[1] * r1 + g[2] * r2;
    float cg = cx * g[0] + cy * g[1] + cz * g[2];
    float s = 2.0f * inv;
    float vgx = v[1] * g[2] - v[2] * g[1];
    float vgy = v[2] * g[0] - v[0] * g[2];
    float vgz = v[0] * g[1] - v[1] * g[0];
    dw += s * (w * c1 + cg - w * gr);
    dx += s * (-c1 * x + c2 * v[0] + c3 * g[0] + w * vgx - gr * x);
    dy += s * (-c1 * y + c2 * v[1] + c3 * g[1] + w * vgy - gr * y);
    dz += s * (-c1 * z + c2 * v[2] + c3 * g[2] + w * vgz - gr * z);
}

// ---------------------------------------------------------------------------
// Pose kernel: k-split, pd in SMEM (69 rows x 256), qs read as bf16. (pure)
#define SPD(r) s_pd[((r) - 3) * 256]
__global__ __launch_bounds__(256, 3) void pose_kernel(const float* __restrict__ tgt,
                                                      const float* __restrict__ stdq,
                                                      const float* __restrict__ meanq,
                                                      const float* __restrict__ offs)
{
    extern __shared__ float s_pd[];          // 69*256 floats
    __shared__ float s_std[CC], s_mean[CC], s_off[JJ * 3];
    __shared__ float s_red[32];
    const int b  = blockIdx.x;
    const int t  = threadIdx.x;
    const int tk = t >> 7;
    const int tt = t & 127;
    if (t < CC) { s_std[t] = stdq[t]; s_mean[t] = meanq[t]; }
    if (t >= 128 && t < 128 + JJ * 3) s_off[t - 128] = offs[b * JJ * 3 + (t - 128)];
    __syncthreads();

    float accR = 0.f, accJ = 0.f, accF = 0.f;

    const __nv_bfloat16* dbase = g_qsb + (size_t)(b * 2 + tk) * CT + tt;
    const float* tbase = tgt + (size_t)(b * 2 + tk) * (2 * CT) + tt;

    {
#pragma unroll
        for (int i = 0; i < 4; i++) {
            float df = __bfloat162float(dbase[(size_t)i * TT]) - tbase[(size_t)i * TT];
            accR += df * df;
        }
        const int leaves[5] = { 10, 11, 15, 22, 23 };
#pragma unroll
        for (int e = 0; e < 5; e++) {
            int j = leaves[e];
#pragma unroll
            for (int i = 0; i < 4; i++) {
                float df = __bfloat162float(dbase[(size_t)(4 * j + i) * TT])
                         - tbase[(size_t)(8 * j + i) * TT];
                accJ += df * df;
            }
        }
    }

    {
        float qD[4], qT[4];
        float pDx, pDy, pDz, pTx, pTy, pTz;

        auto loadPair = [&](int j) {
#pragma unroll
            for (int i = 0; i < 4; i++) {
                int c = 4 * j + i;
                float d  = __bfloat162float(dbase[(size_t)c * TT]);
                float tr = tbase[(size_t)(8 * j + i) * TT];
                float df = d - tr;
                accJ += df * df;
                qD[i] = d * s_std[c] + s_mean[c];
                qT[i] = tr * s_std[c] + s_mean[c];
            }
        };
        auto step = [&](int j) {
            const float* v = s_off + 3 * j;
            float r[3];
            qrot(qD, v, r); pDx += r[0]; pDy += r[1]; pDz += r[2];
            qrot(qT, v, r); pTx += r[0]; pTy += r[1]; pTz += r[2];
            float dx = pDx - pTx, dy = pDy - pTy, dz = pDz - pTz;
            accF += dx * dx + dy * dy + dz * dz;
            (&SPD(3 * j + 0))[t] = pDx;
            (&SPD(3 * j + 1))[t] = pDy;
            (&SPD(3 * j + 2))[t] = pDz;
        };
        auto reset = [&]() {
            pDx = pDy = pDz = pTx = pTy = pTz = 0.f;
            qD[0] = 1.f; qD[1] = qD[2] = qD[3] = 0.f;
            qT[0] = 1.f; qT[1] = qT[2] = qT[3] = 0.f;
        };

        reset();
        step(1); loadPair(1); step(4); loadPair(4); step(7); loadPair(7); step(10);
        reset();
        step(2); loadPair(2); step(5); loadPair(5); step(8); loadPair(8); step(11);
        reset();
        step(3); loadPair(3); step(6); loadPair(6); step(9); loadPair(9);
        float sp[6] = { pDx, pDy, pDz, pTx, pTy, pTz };
        float sqD[4] = { qD[0], qD[1], qD[2], qD[3] };
        float sqT[4] = { qT[0], qT[1], qT[2], qT[3] };
        step(12); loadPair(12); step(15);
        pDx = sp[0]; pDy = sp[1]; pDz = sp[2]; pTx = sp[3]; pTy = sp[4]; pTz = sp[5];
        qD[0] = sqD[0]; qD[1] = sqD[1]; qD[2] = sqD[2]; qD[3] = sqD[3];
        qT[0] = sqT[0]; qT[1] = sqT[1]; qT[2] = sqT[2]; qT[3] = sqT[3];
        step(13); loadPair(13); step(16); loadPair(16); step(18); loadPair(18);
        step(20); loadPair(20); step(22);
        pDx = sp[0]; pDy = sp[1]; pDz = sp[2]; pTx = sp[3]; pTy = sp[4]; pTz = sp[5];
        qD[0] = sqD[0]; qD[1] = sqD[1]; qD[2] = sqD[2]; qD[3] = sqD[3];
        qT[0] = sqT[0]; qT[1] = sqT[1]; qT[2] = sqT[2]; qT[3] = sqT[3];
        step(14); loadPair(14); step(17); loadPair(17); step(19); loadPair(19);
        step(21); loadPair(21); step(23);
    }
    __syncthreads();

    if (tk == 0) {
#pragma unroll
        for (int r = 3; r < 72; r++) {
            float* row = &SPD(r);
            float v = row[tt];
            row[tt] = 2.f * (v - row[tt + 128]);
        }
        const int ch[20] = { 23,22,21,20,19,18,17,16,15,14,13,12,11,10,9,8,7,6,5,4 };
        const int pa[20] = { 21,20,19,18,17,16,14,13,12, 9, 9, 9, 8, 7, 6, 5, 4, 3, 2, 1 };
#pragma unroll
        for (int e = 0; e < 20; e++) {
            int cj = ch[e], pj = pa[e];
#pragma unroll
            for (int i = 0; i < 3; i++)
                (&SPD(3 * pj + i))[tt] += (&SPD(3 * cj + i))[tt];
        }
    }
    __syncthreads();

    __nv_bfloat16* outp = g_dqsb + (size_t)b * CT + tt;
    const __nv_bfloat16* dbase0 = g_qsb + (size_t)(b * 2) * CT + tt;
    auto doParent = [&](int p, int c0, int c1, int c2) {
        float q[4];
#pragma unroll
        for (int i = 0; i < 4; i++) {
            int c = 4 * p + i;
            q[i] = __bfloat162float(dbase0[(size_t)c * TT]) * s_std[c] + s_mean[c];
        }
        float dw = 0.f, dx = 0.f, dy = 0.f, dz = 0.f;
        float gv[3];
        gv[0] = (&SPD(3 * c0 + 0))[tt];
        gv[1] = (&SPD(3 * c0 + 1))[tt];
        gv[2] = (&SPD(3 * c0 + 2))[tt];
        qrot_bwd(q, s_off + 3 * c0, gv, dw, dx, dy, dz);
        if (c1 >= 0) {
            gv[0] = (&SPD(3 * c1 + 0))[tt];
            gv[1] = (&SPD(3 * c1 + 1))[tt];
            gv[2] = (&SPD(3 * c1 + 2))[tt];
            qrot_bwd(q, s_off + 3 * c1, gv, dw, dx, dy, dz);
        }
        if (c2 >= 0) {
            gv[0] = (&SPD(3 * c2 + 0))[tt];
            gv[1] = (&SPD(3 * c2 + 1))[tt];
            gv[2] = (&SPD(3 * c2 + 2))[tt];
            qrot_bwd(q, s_off + 3 * c2, gv, dw, dx, dy, dz);
        }
        outp[(size_t)(4 * p + 0) * TT] = __float2bfloat16_rn(dw * s_std[4 * p + 0]);
        outp[(size_t)(4 * p + 1) * TT] = __float2bfloat16_rn(dx * s_std[4 * p + 1]);
        outp[(size_t)(4 * p + 2) * TT] = __float2bfloat16_rn(dy * s_std[4 * p + 2]);
        outp[(size_t)(4 * p + 3) * TT] = __float2bfloat16_rn(dz * s_std[4 * p + 3]);
    };
    const __nv_bfloat16 bz = __float2bfloat16_rn(0.f);
    if (tk == 0) {
        const int zj[3] = { 0, 10, 11 };
#pragma unroll
        for (int e = 0; e < 3; e++)
#pragma unroll
            for (int i = 0; i < 4; i++)
                outp[(size_t)(4 * zj[e] + i) * TT] = bz;
        doParent(1, 4, -1, -1);  doParent(2, 5, -1, -1);  doParent(3, 6, -1, -1);
        doParent(4, 7, -1, -1);  doParent(5, 8, -1, -1);  doParent(6, 9, -1, -1);
        doParent(7, 10, -1, -1); doParent(8, 11, -1, -1);
        doParent(9, 12, 13, 14);
    } else {
        const int zj[3] = { 15, 22, 23 };
#pragma unroll
        for (int e = 0; e < 3; e++)
#pragma unroll
            for (int i = 0; i < 4; i++)
                outp[(size_t)(4 * zj[e] + i) * TT] = bz;
        doParent(12, 15, -1, -1); doParent(13, 16, -1, -1); doParent(14, 17, -1, -1);
        doParent(16, 18, -1, -1); doParent(17, 19, -1, -1); doParent(18, 20, -1, -1);
        doParent(19, 21, -1, -1); doParent(20, 22, -1, -1); doParent(21, 23, -1, -1);
    }

    float r = blockReduce(accR, s_red);
    if (threadIdx.x == 0) atomicAdd(&g_acc[0], (double)r);
    __syncthreads();
    r = blockReduce(accJ, s_red);
    if (threadIdx.x == 0) atomicAdd(&g_acc[1], (double)r);
    __syncthreads();
    r = blockReduce(accF, s_red);
    if (threadIdx.x == 0) atomicAdd(&g_acc[2], (double)r);
}

// ---------------------------------------------------------------------------
// cons loss only; last arriving block finalizes the output.
__global__ void cons_kernel(const float* __restrict__ lat, float* __restrict__ out)
{
    __shared__ float s_red[32];
    int i = blockIdx.x * blockDim.x + threadIdx.x;
    int b = i >> 8, z = i & 255;
    float d = lat[(size_t)(2 * b) * ZZ + z] - g_grad[i] - lat[(size_t)(2 * b + 1) * ZZ + z];
    float r = blockReduce(d * d, s_red);
    if (threadIdx.x == 0) atomicAdd(&g_acc[5], (double)r);

    if (threadIdx.x == 0) {
        __threadfence();
        unsigned int c = atomicAdd(&g_cnt, 1u);
        if (c == gridDim.x - 1) {
            out[0] = (float)(-0.5 * g_acc[3] / 1024.0) * 0.001f;
            out[1] = (float)(g_acc[0] / 524288.0);
            out[2] = (float)(g_acc[4] / 393216.0);
            out[3] = (float)(g_acc[5] / 131072.0) * 0.1f;
            out[4] = (float)(g_acc[2] / 9437184.0) * 0.1f;
            out[5] = (float)(g_acc[1] / 12058624.0);
        }
    }
}

// ---------------------------------------------------------------------------
extern "C" void kernel_launch(void* const* d_in, const int* in_sizes, int n_in,
                              void* d_out, int out_size)
{
    const float* base  = (const float*)d_in[0];
    const float* tgt   = (const float*)d_in[1];
    const float* idisp = (const float*)d_in[2];
    const float* tdisp = (const float*)d_in[3];
    const float* mu    = (const float*)d_in[4];
    const float* lv    = (const float*)d_in[5];
    const float* lat   = (const float*)d_in[6];
    const float* W     = (const float*)d_in[7];
    const float* meanq = (const float*)d_in[8];
    const float* stdq  = (const float*)d_in[9];
    const float* offs  = (const float*)d_in[10];
    float* out = (float*)d_out;

    cudaFuncSetAttribute(gemm1_tc, cudaFuncAttributeMaxDynamicSharedMemorySize, 37888);
    cudaFuncSetAttribute(gemm2_tc, cudaFuncAttributeMaxDynamicSharedMemorySize, 61440);
    cudaFuncSetAttribute(pose_kernel, cudaFuncAttributeMaxDynamicSharedMemorySize, 70656);

    cvt_kernel<<<6657, 256>>>(W, lat);
    gemm1_tc<<<dim3(96, 8), 256, 37888>>>(base, W);
    pose_kernel<<<BP, 256, 70656>>>(tgt, stdq, meanq, offs);
    gemm2_tc<<<dim3(2, 4, 32), 256, 61440>>>(idisp, tdisp, mu, lv);
    cons_kernel<<<512, 256>>>(lat, out);
}